// round 1
// baseline (speedup 1.0000x reference)
#include <cuda_runtime.h>
#include <math.h>
#include <stdint.h>
#include <stddef.h>

#define DEV __device__ __forceinline__

constexpr int Bc = 2, Sc = 2048, Dc = 512, Hc = 8, HDc = 64, KC = 31;
constexpr int FFc = 2048, Gc = 4, Ec = 2;
constexpr int Nc = Bc * Sc; // 4096 tokens

// ---------------- scratch (static device globals; no allocation) ----------------
__device__ float g_h1[Nc * Dc];       // LN1 output
__device__ float g_x1[Nc * Dc];       // post-conv residual
__device__ float g_h2[Nc * Dc];       // LN2 output
__device__ float g_q[Nc * Dc];
__device__ float g_k[Nc * Dc];
__device__ float g_v[Nc * Dc];
__device__ float g_o[Nc * Dc];        // attention output (pre out-proj)
__device__ float g_x2[Nc * Dc];       // post-attention residual
__device__ float g_scores[(size_t)Bc * Hc * Sc * Sc];   // 256 MB
__device__ float g_hid[(size_t)Nc * Ec * FFc];          // 64 MB
__device__ int   g_perm[Gc * Nc];
__device__ int   g_cnt[Gc];

DEV float gelu_f(float x) {
    const float c0 = 0.7978845608028654f; // sqrt(2/pi)
    float t = c0 * (x + 0.044715f * x * x * x);
    return 0.5f * x * (1.0f + tanhf(t));
}

// ---------------- LayerNorm ----------------
// WHICH==0: src = xin (harness input), dst = g_h1
// WHICH==1: src = g_x1, dst = g_h2
template <int WHICH>
__global__ void ln_kernel(const float* __restrict__ xin,
                          const float* __restrict__ sc,
                          const float* __restrict__ bi) {
    const float* src = (WHICH == 0) ? xin : g_x1;
    float* dst = (WHICH == 0) ? g_h1 : g_h2;
    int row = blockIdx.x;
    const float* xr = src + (size_t)row * Dc;
    float* orow = dst + (size_t)row * Dc;
    int t = threadIdx.x; // 256 threads, 2 elems each
    float a = xr[t], b = xr[t + 256];
    float s = a + b, sq = a * a + b * b;
    __shared__ float sh[16];
#pragma unroll
    for (int o = 16; o; o >>= 1) {
        s += __shfl_xor_sync(0xffffffffu, s, o);
        sq += __shfl_xor_sync(0xffffffffu, sq, o);
    }
    int w = t >> 5;
    if ((t & 31) == 0) { sh[w] = s; sh[8 + w] = sq; }
    __syncthreads();
    if (t == 0) {
        float ts = 0.f, tq = 0.f;
#pragma unroll
        for (int i = 0; i < 8; i++) { ts += sh[i]; tq += sh[8 + i]; }
        float mean = ts * (1.0f / Dc);
        float var = tq * (1.0f / Dc) - mean * mean;
        sh[0] = mean;
        sh[1] = rsqrtf(var + 1e-6f);
    }
    __syncthreads();
    float mean = sh[0], rstd = sh[1];
    orow[t]       = (a - mean) * rstd * sc[t] + bi[t];
    orow[t + 256] = (b - mean) * rstd * sc[t + 256] + bi[t + 256];
}

// ---------------- softmax over last dim of g_scores ----------------
__global__ void softmax_kernel() {
    size_t row = blockIdx.x;
    float* p = g_scores + row * (size_t)Sc;
    int t = threadIdx.x; // 256
    float v[8];
    float mx = -1e30f;
#pragma unroll
    for (int i = 0; i < 8; i++) { v[i] = p[t + (i << 8)]; mx = fmaxf(mx, v[i]); }
    __shared__ float sh[8];
#pragma unroll
    for (int o = 16; o; o >>= 1) mx = fmaxf(mx, __shfl_xor_sync(0xffffffffu, mx, o));
    if ((t & 31) == 0) sh[t >> 5] = mx;
    __syncthreads();
    float m = sh[0];
#pragma unroll
    for (int i = 1; i < 8; i++) m = fmaxf(m, sh[i]);
    __syncthreads();
    float s = 0.f;
#pragma unroll
    for (int i = 0; i < 8; i++) { v[i] = expf(v[i] - m); s += v[i]; }
#pragma unroll
    for (int o = 16; o; o >>= 1) s += __shfl_xor_sync(0xffffffffu, s, o);
    if ((t & 31) == 0) sh[t >> 5] = s;
    __syncthreads();
    float tot = sh[0] + sh[1] + sh[2] + sh[3] + sh[4] + sh[5] + sh[6] + sh[7];
    float inv = 1.0f / tot;
#pragma unroll
    for (int i = 0; i < 8; i++) p[t + (i << 8)] = v[i] * inv;
}

// ---------------- group routing ----------------
__global__ void zero_cnt_kernel() {
    if (threadIdx.x < Gc) g_cnt[threadIdx.x] = 0;
}
__global__ void scatter_kernel(const int* __restrict__ gid) {
    int n = blockIdx.x * 256 + threadIdx.x;
    if (n < Nc) {
        int g = gid[n];
        int p = atomicAdd(&g_cnt[g], 1);
        g_perm[(g << 12) + p] = n;
    }
}

// ---------------- shared-tile store helpers ----------------
// transpose-store a float4 of 4 consecutive-K values: Sm[k_local + j][row_local]
DEV void store_tr8(float (*Sm)[128], float4 v, int tid) {
    int kl = (tid & 1) << 2, l = tid >> 1;
    Sm[kl + 0][l] = v.x; Sm[kl + 1][l] = v.y; Sm[kl + 2][l] = v.z; Sm[kl + 3][l] = v.w;
}
// row-major B tile load: Bs[kk][c..c+3] from base[(k0+kk)*ldb + n0 + c]
DEV void loadB_rm8(float (*Bs)[128], const float* __restrict__ base, int ldb,
                   int n0, int k0, int tid) {
    int kk = tid >> 5, c = (tid & 31) << 2;
    *(float4*)&Bs[kk][c] = *(const float4*)&base[(size_t)(k0 + kk) * ldb + n0 + c];
}

// ---------------- generic 128x128x8 SGEMM, 8x8 microtile ----------------
template <class P>
__global__ __launch_bounds__(256) void gemm128(P p) {
    if (p.skip()) return;
    __shared__ __align__(16) float As[8][128];
    __shared__ __align__(16) float Bs[8][128];
    int tid = threadIdx.x;
    int m0 = blockIdx.y * 128, n0 = blockIdx.x * 128, z = blockIdx.z;
    float acc[8][8];
#pragma unroll
    for (int i = 0; i < 8; i++)
#pragma unroll
        for (int j = 0; j < 8; j++) acc[i][j] = 0.f;
    int Kt = p.K();
    for (int k0 = 0; k0 < Kt; k0 += 8) {
        p.loadA(As, m0, k0, tid, z);
        p.loadB(Bs, n0, k0, tid, z);
        __syncthreads();
        int tr = (tid >> 4) << 3, tc = (tid & 15) << 3;
#pragma unroll
        for (int kk = 0; kk < 8; kk++) {
            float4 a0 = *(const float4*)&As[kk][tr];
            float4 a1 = *(const float4*)&As[kk][tr + 4];
            float4 b0 = *(const float4*)&Bs[kk][tc];
            float4 b1 = *(const float4*)&Bs[kk][tc + 4];
            float av[8] = {a0.x, a0.y, a0.z, a0.w, a1.x, a1.y, a1.z, a1.w};
            float bv[8] = {b0.x, b0.y, b0.z, b0.w, b1.x, b1.y, b1.z, b1.w};
#pragma unroll
            for (int i = 0; i < 8; i++)
#pragma unroll
                for (int j = 0; j < 8; j++) acc[i][j] += av[i] * bv[j];
        }
        __syncthreads();
    }
    p.store(acc, m0, n0, tid, z);
}

// ---------------- generic 64x64x16 SGEMM (for AV, N=64) ----------------
DEV void store_tr16(float (*Sm)[64], float4 v, int tid) {
    int kl = (tid & 3) << 2, l = tid >> 2;
    Sm[kl + 0][l] = v.x; Sm[kl + 1][l] = v.y; Sm[kl + 2][l] = v.z; Sm[kl + 3][l] = v.w;
}
template <class P>
__global__ __launch_bounds__(256) void gemm64(P p) {
    __shared__ __align__(16) float As[16][64];
    __shared__ __align__(16) float Bs[16][64];
    int tid = threadIdx.x;
    int m0 = blockIdx.y * 64, n0 = blockIdx.x * 64, z = blockIdx.z;
    float acc[4][4];
#pragma unroll
    for (int i = 0; i < 4; i++)
#pragma unroll
        for (int j = 0; j < 4; j++) acc[i][j] = 0.f;
    int Kt = p.K();
    for (int k0 = 0; k0 < Kt; k0 += 16) {
        p.loadA(As, m0, k0, tid, z);
        p.loadB(Bs, n0, k0, tid, z);
        __syncthreads();
        int tr = (tid >> 4) << 2, tc = (tid & 15) << 2;
#pragma unroll
        for (int kk = 0; kk < 16; kk++) {
            float4 a = *(const float4*)&As[kk][tr];
            float4 b = *(const float4*)&Bs[kk][tc];
            float av[4] = {a.x, a.y, a.z, a.w};
            float bv[4] = {b.x, b.y, b.z, b.w};
#pragma unroll
            for (int i = 0; i < 4; i++)
#pragma unroll
                for (int j = 0; j < 4; j++) acc[i][j] += av[i] * bv[j];
        }
        __syncthreads();
    }
    p.store(acc, m0, n0, tid, z);
}

// ================= problem functors =================

// ---- Conv1d(SAME, K=31) as implicit GEMM: K_total = 31*512, A gathered with shift + zero pad.
// epilogue: gelu(acc + cb) + x  -> g_x1
struct ConvProb {
    const float* ck;    // [31,512,512]
    const float* cb;    // [512]
    const float* xres;  // original x
    DEV int K() const { return KC * Dc; } // 15872
    DEV bool skip() const { return false; }
    DEV void loadA(float (*As)[128], int m0, int k0, int tid, int) const {
        int m = m0 + (tid >> 1);
        int k = k0 + ((tid & 1) << 2);
        int kk = k >> 9, ci = k & 511;
        int b = m >> 11, s = m & 2047;
        int sr = s + kk - 15;
        float4 v = make_float4(0.f, 0.f, 0.f, 0.f);
        if ((unsigned)sr < (unsigned)Sc)
            v = *(const float4*)&g_h1[(size_t)((b << 11) + sr) * Dc + ci];
        store_tr8(As, v, tid);
    }
    DEV void loadB(float (*Bs)[128], int n0, int k0, int tid, int) const {
        loadB_rm8(Bs, ck, Dc, n0, k0, tid);
    }
    DEV void store(float (&acc)[8][8], int m0, int n0, int tid, int) const {
        int tr = (tid >> 4) << 3, tc = (tid & 15) << 3;
#pragma unroll
        for (int i = 0; i < 8; i++) {
            int m = m0 + tr + i;
#pragma unroll
            for (int j = 0; j < 8; j++) {
                int c = n0 + tc + j;
                float val = acc[i][j] + cb[c];
                g_x1[(size_t)m * Dc + c] = gelu_f(val) + xres[(size_t)m * Dc + c];
            }
        }
    }
};

// ---- QKV: g_h2 [4096,512] @ w{q,k,v} [512,512] + bias, z selects which
struct QKVProb {
    const float* w[3];
    const float* b[3];
    DEV int K() const { return Dc; }
    DEV bool skip() const { return false; }
    DEV void loadA(float (*As)[128], int m0, int k0, int tid, int) const {
        int m = m0 + (tid >> 1), k = k0 + ((tid & 1) << 2);
        float4 v = *(const float4*)&g_h2[(size_t)m * Dc + k];
        store_tr8(As, v, tid);
    }
    DEV void loadB(float (*Bs)[128], int n0, int k0, int tid, int z) const {
        loadB_rm8(Bs, w[z], Dc, n0, k0, tid);
    }
    DEV void store(float (&acc)[8][8], int m0, int n0, int tid, int z) const {
        float* outs[3] = {g_q, g_k, g_v};
        float* o = outs[z];
        const float* bias = b[z];
        int tr = (tid >> 4) << 3, tc = (tid & 15) << 3;
#pragma unroll
        for (int i = 0; i < 8; i++) {
            int m = m0 + tr + i;
#pragma unroll
            for (int j = 0; j < 8; j++) {
                int c = n0 + tc + j;
                o[(size_t)m * Dc + c] = acc[i][j] + bias[c];
            }
        }
    }
};

// ---- scores[bh,q,s] = 0.125 * Q . K ; z = b*8+h ; K dim = 64
struct ScoreProb {
    DEV int K() const { return HDc; }
    DEV bool skip() const { return false; }
    DEV void loadA(float (*As)[128], int m0, int k0, int tid, int z) const {
        int b = z >> 3, h = z & 7;
        int m = m0 + (tid >> 1), k = k0 + ((tid & 1) << 2);
        float4 v = *(const float4*)&g_q[(size_t)((b << 11) + m) * Dc + (h << 6) + k];
        store_tr8(As, v, tid);
    }
    DEV void loadB(float (*Bs)[128], int n0, int k0, int tid, int z) const {
        int b = z >> 3, h = z & 7;
        int sidx = n0 + (tid >> 1), k = k0 + ((tid & 1) << 2);
        float4 v = *(const float4*)&g_k[(size_t)((b << 11) + sidx) * Dc + (h << 6) + k];
        store_tr8(Bs, v, tid);
    }
    DEV void store(float (&acc)[8][8], int m0, int n0, int tid, int z) const {
        int tr = (tid >> 4) << 3, tc = (tid & 15) << 3;
        float* base = g_scores + (size_t)z * Sc * Sc;
#pragma unroll
        for (int i = 0; i < 8; i++) {
            int m = m0 + tr + i;
#pragma unroll
            for (int j = 0; j < 8; j++) {
                int c = n0 + tc + j;
                base[(size_t)m * Sc + c] = acc[i][j] * 0.125f;
            }
        }
    }
};

// ---- AV: o[b,q,h,:] = att[bh,q,:] @ V[b,:,h,:] ; M=2048, N=64, K=2048 per bh
struct AVProb {
    DEV int K() const { return Sc; }
    DEV void loadA(float (*As)[64], int m0, int k0, int tid, int z) const {
        int m = m0 + (tid >> 2), k = k0 + ((tid & 3) << 2);
        float4 v = *(const float4*)&g_scores[((size_t)z * Sc + m) * Sc + k];
        store_tr16(As, v, tid);
    }
    DEV void loadB(float (*Bs)[64], int n0, int k0, int tid, int z) const {
        int b = z >> 3, h = z & 7;
        int kk = tid >> 4, c = (tid & 15) << 2;
        *(float4*)&Bs[kk][c] =
            *(const float4*)&g_v[(size_t)((b << 11) + k0 + kk) * Dc + (h << 6) + n0 + c];
    }
    DEV void store(float (&acc)[4][4], int m0, int n0, int tid, int z) const {
        int b = z >> 3, h = z & 7;
        int tr = (tid >> 4) << 2, tc = (tid & 15) << 2;
#pragma unroll
        for (int i = 0; i < 4; i++) {
            int m = m0 + tr + i;
#pragma unroll
            for (int j = 0; j < 4; j++) {
                int c = n0 + tc + j;
                g_o[(size_t)((b << 11) + m) * Dc + (h << 6) + c] = acc[i][j];
            }
        }
    }
};

// ---- out proj: g_o @ wo + bo + g_x1 -> g_x2
struct OutProb {
    const float* wo;
    const float* bo;
    DEV int K() const { return Dc; }
    DEV bool skip() const { return false; }
    DEV void loadA(float (*As)[128], int m0, int k0, int tid, int) const {
        int m = m0 + (tid >> 1), k = k0 + ((tid & 1) << 2);
        float4 v = *(const float4*)&g_o[(size_t)m * Dc + k];
        store_tr8(As, v, tid);
    }
    DEV void loadB(float (*Bs)[128], int n0, int k0, int tid, int) const {
        loadB_rm8(Bs, wo, Dc, n0, k0, tid);
    }
    DEV void store(float (&acc)[8][8], int m0, int n0, int tid, int) const {
        int tr = (tid >> 4) << 3, tc = (tid & 15) << 3;
#pragma unroll
        for (int i = 0; i < 8; i++) {
            int m = m0 + tr + i;
#pragma unroll
            for (int j = 0; j < 8; j++) {
                int c = n0 + tc + j;
                g_x2[(size_t)m * Dc + c] = acc[i][j] + bo[c] + g_x1[(size_t)m * Dc + c];
            }
        }
    }
};

// ---- MoE expert GEMM1: hid[tok,e,:] = gelu(x2[tok] @ w1[g,e] + b1[g,e]) ; z = g*2+e
struct Moe1Prob {
    const float* w1;  // [G,E,512,2048]
    const float* b1;  // [G,E,2048]
    DEV int K() const { return Dc; }
    DEV bool skip() const { return (int)(blockIdx.y * 128) >= g_cnt[blockIdx.z >> 1]; }
    DEV void loadA(float (*As)[128], int m0, int k0, int tid, int z) const {
        int g = z >> 1;
        int i = m0 + (tid >> 1);
        float4 v = make_float4(0.f, 0.f, 0.f, 0.f);
        if (i < g_cnt[g]) {
            int tok = g_perm[(g << 12) + i];
            v = *(const float4*)&g_x2[(size_t)tok * Dc + k0 + ((tid & 1) << 2)];
        }
        store_tr8(As, v, tid);
    }
    DEV void loadB(float (*Bs)[128], int n0, int k0, int tid, int z) const {
        loadB_rm8(Bs, w1 + (size_t)z * Dc * FFc, FFc, n0, k0, tid);
    }
    DEV void store(float (&acc)[8][8], int m0, int n0, int tid, int z) const {
        int g = z >> 1, e = z & 1;
        int cnt = g_cnt[g];
        int tr = (tid >> 4) << 3, tc = (tid & 15) << 3;
#pragma unroll
        for (int i = 0; i < 8; i++) {
            int idx = m0 + tr + i;
            if (idx >= cnt) continue;
            int tok = g_perm[(g << 12) + idx];
#pragma unroll
            for (int j = 0; j < 8; j++) {
                int c = n0 + tc + j;
                g_hid[(size_t)tok * (Ec * FFc) + (e << 11) + c] =
                    gelu_f(acc[i][j] + b1[(size_t)z * FFc + c]);
            }
        }
    }
};

// ---- MoE GEMM2 (fold expert-mean into K=E*FF=4096): out[tok] = 0.5*Σ_{e,ff} hid·w2 + 0.5*Σ_e b2 + x2
struct Moe2Prob {
    const float* w2;  // [G,E,2048,512]
    const float* b2;  // [G,E,512]
    float* out;
    DEV int K() const { return Ec * FFc; } // 4096
    DEV bool skip() const { return (int)(blockIdx.y * 128) >= g_cnt[blockIdx.z]; }
    DEV void loadA(float (*As)[128], int m0, int k0, int tid, int z) const {
        int g = z;
        int i = m0 + (tid >> 1);
        float4 v = make_float4(0.f, 0.f, 0.f, 0.f);
        if (i < g_cnt[g]) {
            int tok = g_perm[(g << 12) + i];
            v = *(const float4*)&g_hid[(size_t)tok * (Ec * FFc) + k0 + ((tid & 1) << 2)];
        }
        store_tr8(As, v, tid);
    }
    DEV void loadB(float (*Bs)[128], int n0, int k0, int tid, int z) const {
        // w2[g] flattened: row index (e*2048+ff), ld = 512 — exactly K-major
        loadB_rm8(Bs, w2 + (size_t)z * Ec * FFc * Dc, Dc, n0, k0, tid);
    }
    DEV void store(float (&acc)[8][8], int m0, int n0, int tid, int z) const {
        int g = z;
        int cnt = g_cnt[g];
        int tr = (tid >> 4) << 3, tc = (tid & 15) << 3;
#pragma unroll
        for (int i = 0; i < 8; i++) {
            int idx = m0 + tr + i;
            if (idx >= cnt) continue;
            int tok = g_perm[(g << 12) + idx];
#pragma unroll
            for (int j = 0; j < 8; j++) {
                int c = n0 + tc + j;
                float bsum = b2[(size_t)(g * 2) * Dc + c] + b2[(size_t)(g * 2 + 1) * Dc + c];
                out[(size_t)tok * Dc + c] =
                    0.5f * acc[i][j] + 0.5f * bsum + g_x2[(size_t)tok * Dc + c];
            }
        }
    }
};

// ================= launch =================
extern "C" void kernel_launch(void* const* d_in, const int* in_sizes, int n_in,
                              void* d_out, int out_size) {
    const float* x    = (const float*)d_in[0];
    const int*   gid  = (const int*)d_in[1];
    const float* ln1s = (const float*)d_in[2];
    const float* ln1b = (const float*)d_in[3];
    const float* ck   = (const float*)d_in[4];
    const float* cb   = (const float*)d_in[5];
    const float* ln2s = (const float*)d_in[6];
    const float* ln2b = (const float*)d_in[7];
    const float* wq   = (const float*)d_in[8];
    const float* bq   = (const float*)d_in[9];
    const float* wk   = (const float*)d_in[10];
    const float* bk   = (const float*)d_in[11];
    const float* wv   = (const float*)d_in[12];
    const float* bv   = (const float*)d_in[13];
    const float* wo   = (const float*)d_in[14];
    const float* bo   = (const float*)d_in[15];
    const float* w1   = (const float*)d_in[16];
    const float* b1   = (const float*)d_in[17];
    const float* w2   = (const float*)d_in[18];
    const float* b2   = (const float*)d_in[19];
    float* out = (float*)d_out;

    // 1. LN1
    ln_kernel<0><<<Nc, 256>>>(x, ln1s, ln1b);
    // 2. conv + gelu + residual
    {
        ConvProb p{ck, cb, x};
        gemm128<ConvProb><<<dim3(Dc / 128, Nc / 128, 1), 256>>>(p);
    }
    // 3. LN2
    ln_kernel<1><<<Nc, 256>>>(x, ln2s, ln2b);
    // 4. QKV
    {
        QKVProb p;
        p.w[0] = wq; p.w[1] = wk; p.w[2] = wv;
        p.b[0] = bq; p.b[1] = bk; p.b[2] = bv;
        gemm128<QKVProb><<<dim3(Dc / 128, Nc / 128, 3), 256>>>(p);
    }
    // 5. scores
    {
        ScoreProb p;
        gemm128<ScoreProb><<<dim3(Sc / 128, Sc / 128, Bc * Hc), 256>>>(p);
    }
    // 6. softmax
    softmax_kernel<<<Bc * Hc * Sc, 256>>>();
    // 7. AV
    {
        AVProb p;
        gemm64<AVProb><<<dim3(1, Sc / 64, Bc * Hc), 256>>>(p);
    }
    // 8. out proj + residual
    {
        OutProb p{wo, bo};
        gemm128<OutProb><<<dim3(Dc / 128, Nc / 128, 1), 256>>>(p);
    }
    // 9. group routing
    zero_cnt_kernel<<<1, 32>>>();
    scatter_kernel<<<Nc / 256, 256>>>(gid);
    // 10. MoE GEMM1 (per group+expert, gathered rows)
    {
        Moe1Prob p{w1, b1};
        gemm128<Moe1Prob><<<dim3(FFc / 128, Nc / 128, Gc * Ec), 256>>>(p);
    }
    // 11. MoE GEMM2 (expert-mean folded into K) + residual -> d_out
    {
        Moe2Prob p{w2, b2, out};
        gemm128<Moe2Prob><<<dim3(Dc / 128, Nc / 128, Gc), 256>>>(p);
    }
}

// round 2
// speedup vs baseline: 2.8094x; 2.8094x over previous
#include <cuda_runtime.h>
#include <math.h>
#include <stdint.h>
#include <stddef.h>

#define DEV __device__ __forceinline__

constexpr int Bc = 2, Sc = 2048, Dc = 512, Hc = 8, HDc = 64, KC = 31;
constexpr int FFc = 2048, Gc = 4, Ec = 2;
constexpr int Nc = Bc * Sc; // 4096 tokens

// ---------------- scratch ----------------
__device__ float g_h1[Nc * Dc];
__device__ float g_x1[Nc * Dc];
__device__ float g_h2[Nc * Dc];
__device__ float g_q[Nc * Dc];
__device__ float g_k[Nc * Dc];
__device__ float g_v[Nc * Dc];
__device__ float g_o[Nc * Dc];
__device__ float g_x2[Nc * Dc];
__device__ float g_scores[(size_t)Bc * Hc * Sc * Sc];   // 256 MB
__device__ float g_hid[(size_t)Nc * Ec * FFc];          // 64 MB
__device__ int   g_perm[Gc * Nc];
__device__ int   g_cnt[Gc];

DEV float gelu_f(float x) {
    const float c0 = 0.7978845608028654f;
    float t = c0 * (x + 0.044715f * x * x * x);
    return 0.5f * x * (1.0f + tanhf(t));
}

DEV float cv_tf32(float x) {
    uint32_t r;
    asm("cvt.rna.tf32.f32 %0, %1;" : "=r"(r) : "f"(x));
    return __uint_as_float(r);
}

DEV void mma_tf32(float (&c)[4], const uint32_t (&a)[4], const uint32_t (&b)[2]) {
    asm volatile(
        "mma.sync.aligned.m16n8k8.row.col.f32.tf32.tf32.f32 "
        "{%0,%1,%2,%3},{%4,%5,%6,%7},{%8,%9},{%0,%1,%2,%3};\n"
        : "+f"(c[0]), "+f"(c[1]), "+f"(c[2]), "+f"(c[3])
        : "r"(a[0]), "r"(a[1]), "r"(a[2]), "r"(a[3]), "r"(b[0]), "r"(b[1]));
}

// ---------------- LayerNorm ----------------
template <int WHICH>
__global__ void ln_kernel(const float* __restrict__ xin,
                          const float* __restrict__ sc,
                          const float* __restrict__ bi) {
    const float* src = (WHICH == 0) ? xin : g_x1;
    float* dst = (WHICH == 0) ? g_h1 : g_h2;
    int row = blockIdx.x;
    const float* xr = src + (size_t)row * Dc;
    float* orow = dst + (size_t)row * Dc;
    int t = threadIdx.x;
    float a = xr[t], b = xr[t + 256];
    float s = a + b, sq = a * a + b * b;
    __shared__ float sh[16];
#pragma unroll
    for (int o = 16; o; o >>= 1) {
        s += __shfl_xor_sync(0xffffffffu, s, o);
        sq += __shfl_xor_sync(0xffffffffu, sq, o);
    }
    int w = t >> 5;
    if ((t & 31) == 0) { sh[w] = s; sh[8 + w] = sq; }
    __syncthreads();
    if (t == 0) {
        float ts = 0.f, tq = 0.f;
#pragma unroll
        for (int i = 0; i < 8; i++) { ts += sh[i]; tq += sh[8 + i]; }
        float mean = ts * (1.0f / Dc);
        float var = tq * (1.0f / Dc) - mean * mean;
        sh[0] = mean;
        sh[1] = rsqrtf(var + 1e-6f);
    }
    __syncthreads();
    float mean = sh[0], rstd = sh[1];
    orow[t]       = (a - mean) * rstd * sc[t] + bi[t];
    orow[t + 256] = (b - mean) * rstd * sc[t + 256] + bi[t + 256];
}

// ---------------- softmax ----------------
__global__ void softmax_kernel() {
    size_t row = blockIdx.x;
    float* p = g_scores + row * (size_t)Sc;
    int t = threadIdx.x;
    float v[8];
    float mx = -1e30f;
#pragma unroll
    for (int i = 0; i < 8; i++) { v[i] = p[t + (i << 8)]; mx = fmaxf(mx, v[i]); }
    __shared__ float sh[8];
#pragma unroll
    for (int o = 16; o; o >>= 1) mx = fmaxf(mx, __shfl_xor_sync(0xffffffffu, mx, o));
    if ((t & 31) == 0) sh[t >> 5] = mx;
    __syncthreads();
    float m = sh[0];
#pragma unroll
    for (int i = 1; i < 8; i++) m = fmaxf(m, sh[i]);
    __syncthreads();
    float s = 0.f;
#pragma unroll
    for (int i = 0; i < 8; i++) { v[i] = expf(v[i] - m); s += v[i]; }
#pragma unroll
    for (int o = 16; o; o >>= 1) s += __shfl_xor_sync(0xffffffffu, s, o);
    if ((t & 31) == 0) sh[t >> 5] = s;
    __syncthreads();
    float tot = sh[0] + sh[1] + sh[2] + sh[3] + sh[4] + sh[5] + sh[6] + sh[7];
    float inv = 1.0f / tot;
#pragma unroll
    for (int i = 0; i < 8; i++) p[t + (i << 8)] = v[i] * inv;
}

// ---------------- routing ----------------
__global__ void zero_cnt_kernel() {
    if (threadIdx.x < Gc) g_cnt[threadIdx.x] = 0;
}
__global__ void scatter_kernel(const int* __restrict__ gid) {
    int n = blockIdx.x * 256 + threadIdx.x;
    if (n < Nc) {
        int g = gid[n];
        int p = atomicAdd(&g_cnt[g], 1);
        g_perm[(g << 12) + p] = n;
    }
}

// ---------------- shared fill helpers ----------------
// A smem: As[m*20 + k], 128 rows, 16 k, stride 20 (conflict-free frag reads)
// B smem: Bs[k*(NT+8) + n], 16 k, NT cols

DEV void ldA_dense(float4 (&ra)[2], const float* __restrict__ base, size_t ld,
                   int m0, int k0, int tid) {
    int m = m0 + (tid >> 1), kb = k0 + ((tid & 1) << 2);
    const float* p = &base[(size_t)m * ld + kb];
    ra[0] = *(const float4*)p;
    ra[1] = *(const float4*)(p + 8);
}
DEV void stsA(float* As, const float4 (&ra)[2], int tid) {
    int m = tid >> 1, kb = (tid & 1) << 2;
    float* p = &As[m * 20 + kb];
    p[0] = cv_tf32(ra[0].x); p[1] = cv_tf32(ra[0].y);
    p[2] = cv_tf32(ra[0].z); p[3] = cv_tf32(ra[0].w);
    p[8] = cv_tf32(ra[1].x); p[9] = cv_tf32(ra[1].y);
    p[10] = cv_tf32(ra[1].z); p[11] = cv_tf32(ra[1].w);
}
DEV void ldB_dense128(float4 (&rb)[2], const float* __restrict__ base, size_t ld,
                      int n0, int k0, int tid) {
    int kk = k0 + (tid >> 4), c = n0 + ((tid & 15) << 3);
    const float* p = &base[(size_t)kk * ld + c];
    rb[0] = *(const float4*)p;
    rb[1] = *(const float4*)(p + 4);
}
DEV void stsB128(float* Bs, const float4 (&rb)[2], int tid) {
    int kk = tid >> 4, c = (tid & 15) << 3;
    float* p = &Bs[kk * 136 + c];
    p[0] = cv_tf32(rb[0].x); p[1] = cv_tf32(rb[0].y);
    p[2] = cv_tf32(rb[0].z); p[3] = cv_tf32(rb[0].w);
    p[4] = cv_tf32(rb[1].x); p[5] = cv_tf32(rb[1].y);
    p[6] = cv_tf32(rb[1].z); p[7] = cv_tf32(rb[1].w);
}
DEV void ldB_dense64(float4 (&rb)[2], const float* __restrict__ base, size_t ld,
                     int n0, int k0, int tid) {
    int kk = k0 + (tid >> 4), c = n0 + ((tid & 15) << 2);
    rb[0] = *(const float4*)&base[(size_t)kk * ld + c];
}
DEV void stsB64(float* Bs, const float4 (&rb)[2], int tid) {
    int kk = tid >> 4, c = (tid & 15) << 2;
    float* p = &Bs[kk * 72 + c];
    p[0] = cv_tf32(rb[0].x); p[1] = cv_tf32(rb[0].y);
    p[2] = cv_tf32(rb[0].z); p[3] = cv_tf32(rb[0].w);
}
// transpose fill for K-major B (rows are n, cols are k): used by scores
DEV void ldB_tr(float4 (&rb)[2], const float* __restrict__ base, size_t ld,
                int n0, int k0, int tid) {
    int n = n0 + (tid >> 1), kb = k0 + ((tid & 1) << 2);
    const float* p = &base[(size_t)n * ld + kb];
    rb[0] = *(const float4*)p;
    rb[1] = *(const float4*)(p + 8);
}
DEV void stsB_tr128(float* Bs, const float4 (&rb)[2], int tid) {
    int n = tid >> 1, kb = (tid & 1) << 2;
    Bs[(kb + 0) * 136 + n] = cv_tf32(rb[0].x);
    Bs[(kb + 1) * 136 + n] = cv_tf32(rb[0].y);
    Bs[(kb + 2) * 136 + n] = cv_tf32(rb[0].z);
    Bs[(kb + 3) * 136 + n] = cv_tf32(rb[0].w);
    Bs[(kb + 8) * 136 + n] = cv_tf32(rb[1].x);
    Bs[(kb + 9) * 136 + n] = cv_tf32(rb[1].y);
    Bs[(kb + 10) * 136 + n] = cv_tf32(rb[1].z);
    Bs[(kb + 11) * 136 + n] = cv_tf32(rb[1].w);
}

// ---------------- generic MMA GEMM (M tile 128, N tile NT in {128,64}, K step 16) ----------------
template <int NT, class P>
__global__ __launch_bounds__(256) void gemm_mma(P p) {
    if (p.skip()) return;
    constexpr int BSTR = NT + 8;
    constexpr int NF = NT / 32;        // n-fragments per warp
    __shared__ __align__(16) float As[128 * 20];
    __shared__ __align__(16) float Bs[16 * BSTR];
    int tid = threadIdx.x, lane = tid & 31, warp = tid >> 5;
    int m0 = blockIdx.y * 128, n0 = blockIdx.x * NT, z = blockIdx.z;
    int wm = warp >> 2, wn = warp & 3;
    int g = lane >> 2, t4 = lane & 3;

    float acc[4][NF][4];
#pragma unroll
    for (int i = 0; i < 4; i++)
#pragma unroll
        for (int j = 0; j < NF; j++)
#pragma unroll
            for (int q = 0; q < 4; q++) acc[i][j][q] = 0.f;

    float4 ra[2], rb[2];
    int Kt = p.K();
    p.loadA(ra, m0, 0, tid, z);
    p.loadB(rb, n0, 0, tid, z);

    for (int k0 = 0; k0 < Kt; k0 += 16) {
        p.storeA(As, ra, tid);
        p.storeB(Bs, rb, tid);
        __syncthreads();
        if (k0 + 16 < Kt) {
            p.loadA(ra, m0, k0 + 16, tid, z);
            p.loadB(rb, n0, k0 + 16, tid, z);
        }
#pragma unroll
        for (int kk = 0; kk < 16; kk += 8) {
            uint32_t a[4][4], b[NF][2];
#pragma unroll
            for (int i = 0; i < 4; i++) {
                const float* ap = &As[(wm * 64 + i * 16 + g) * 20 + kk + t4];
                a[i][0] = __float_as_uint(ap[0]);
                a[i][1] = __float_as_uint(ap[8 * 20]);
                a[i][2] = __float_as_uint(ap[4]);
                a[i][3] = __float_as_uint(ap[8 * 20 + 4]);
            }
#pragma unroll
            for (int j = 0; j < NF; j++) {
                const float* bp = &Bs[(kk + t4) * BSTR + wn * (NT / 4) + j * 8 + g];
                b[j][0] = __float_as_uint(bp[0]);
                b[j][1] = __float_as_uint(bp[4 * BSTR]);
            }
#pragma unroll
            for (int i = 0; i < 4; i++)
#pragma unroll
                for (int j = 0; j < NF; j++) mma_tf32(acc[i][j], a[i], b[j]);
        }
        __syncthreads();
    }
    // epilogue
#pragma unroll
    for (int i = 0; i < 4; i++) {
        int r0 = m0 + wm * 64 + i * 16 + g;
#pragma unroll
        for (int j = 0; j < NF; j++) {
            int c = n0 + wn * (NT / 4) + j * 8 + 2 * t4;
            p.store2(r0, c, acc[i][j][0], acc[i][j][1], z);
            p.store2(r0 + 8, c, acc[i][j][2], acc[i][j][3], z);
        }
    }
}

// ================= functors =================

struct ConvProb {
    const float* ck;
    const float* cb;
    const float* xres;
    DEV int K() const { return KC * Dc; }
    DEV bool skip() const { return false; }
    DEV void loadA(float4 (&ra)[2], int m0, int k0, int tid, int) const {
        int m = m0 + (tid >> 1);
        int b = m >> 11, s = m & 2047;
        int k = k0 + ((tid & 1) << 2);
        int kk = k >> 9, ci = k & 511;
        int sr = s + kk - 15;
        if ((unsigned)sr < (unsigned)Sc) {
            const float* p = &g_h1[(size_t)((b << 11) + sr) * Dc + ci];
            ra[0] = *(const float4*)p;
            ra[1] = *(const float4*)(p + 8);
        } else {
            ra[0] = ra[1] = make_float4(0.f, 0.f, 0.f, 0.f);
        }
    }
    DEV void storeA(float* As, const float4 (&ra)[2], int tid) const { stsA(As, ra, tid); }
    DEV void loadB(float4 (&rb)[2], int n0, int k0, int tid, int) const {
        ldB_dense128(rb, ck, Dc, n0, k0, tid);
    }
    DEV void storeB(float* Bs, const float4 (&rb)[2], int tid) const { stsB128(Bs, rb, tid); }
    DEV void store2(int m, int c, float v0, float v1, int) const {
        size_t o = (size_t)m * Dc + c;
        g_x1[o]     = gelu_f(v0 + cb[c])     + xres[o];
        g_x1[o + 1] = gelu_f(v1 + cb[c + 1]) + xres[o + 1];
    }
};

struct QKVProb {
    const float* w[3];
    const float* b[3];
    DEV int K() const { return Dc; }
    DEV bool skip() const { return false; }
    DEV void loadA(float4 (&ra)[2], int m0, int k0, int tid, int) const {
        ldA_dense(ra, g_h2, Dc, m0, k0, tid);
    }
    DEV void storeA(float* As, const float4 (&ra)[2], int tid) const { stsA(As, ra, tid); }
    DEV void loadB(float4 (&rb)[2], int n0, int k0, int tid, int z) const {
        ldB_dense128(rb, w[z], Dc, n0, k0, tid);
    }
    DEV void storeB(float* Bs, const float4 (&rb)[2], int tid) const { stsB128(Bs, rb, tid); }
    DEV void store2(int m, int c, float v0, float v1, int z) const {
        float* outs[3] = {g_q, g_k, g_v};
        float* o = outs[z];
        const float* bias = b[z];
        size_t off = (size_t)m * Dc + c;
        o[off] = v0 + bias[c];
        o[off + 1] = v1 + bias[c + 1];
    }
};

struct ScoreProb {
    DEV int K() const { return HDc; }
    DEV bool skip() const { return false; }
    DEV void loadA(float4 (&ra)[2], int m0, int k0, int tid, int z) const {
        int b = z >> 3, h = z & 7;
        ldA_dense(ra, g_q + (size_t)(b << 11) * Dc + (h << 6), Dc, m0, k0, tid);
    }
    DEV void storeA(float* As, const float4 (&ra)[2], int tid) const { stsA(As, ra, tid); }
    DEV void loadB(float4 (&rb)[2], int n0, int k0, int tid, int z) const {
        int b = z >> 3, h = z & 7;
        ldB_tr(rb, g_k + (size_t)(b << 11) * Dc + (h << 6), Dc, n0, k0, tid);
    }
    DEV void storeB(float* Bs, const float4 (&rb)[2], int tid) const { stsB_tr128(Bs, rb, tid); }
    DEV void store2(int m, int c, float v0, float v1, int z) const {
        float* base = g_scores + (size_t)z * Sc * Sc + (size_t)m * Sc + c;
        base[0] = v0 * 0.125f;
        base[1] = v1 * 0.125f;
    }
};

struct AVProb {
    DEV int K() const { return Sc; }
    DEV bool skip() const { return false; }
    DEV void loadA(float4 (&ra)[2], int m0, int k0, int tid, int z) const {
        ldA_dense(ra, g_scores + (size_t)z * Sc * Sc, Sc, m0, k0, tid);
    }
    DEV void storeA(float* As, const float4 (&ra)[2], int tid) const { stsA(As, ra, tid); }
    DEV void loadB(float4 (&rb)[2], int n0, int k0, int tid, int z) const {
        int b = z >> 3, h = z & 7;
        ldB_dense64(rb, g_v + (size_t)(b << 11) * Dc + (h << 6), Dc, n0, k0, tid);
    }
    DEV void storeB(float* Bs, const float4 (&rb)[2], int tid) const { stsB64(Bs, rb, tid); }
    DEV void store2(int m, int c, float v0, float v1, int z) const {
        int b = z >> 3, h = z & 7;
        size_t o = (size_t)((b << 11) + m) * Dc + (h << 6) + c;
        g_o[o] = v0;
        g_o[o + 1] = v1;
    }
};

struct OutProb {
    const float* wo;
    const float* bo;
    DEV int K() const { return Dc; }
    DEV bool skip() const { return false; }
    DEV void loadA(float4 (&ra)[2], int m0, int k0, int tid, int) const {
        ldA_dense(ra, g_o, Dc, m0, k0, tid);
    }
    DEV void storeA(float* As, const float4 (&ra)[2], int tid) const { stsA(As, ra, tid); }
    DEV void loadB(float4 (&rb)[2], int n0, int k0, int tid, int) const {
        ldB_dense128(rb, wo, Dc, n0, k0, tid);
    }
    DEV void storeB(float* Bs, const float4 (&rb)[2], int tid) const { stsB128(Bs, rb, tid); }
    DEV void store2(int m, int c, float v0, float v1, int) const {
        size_t o = (size_t)m * Dc + c;
        g_x2[o]     = v0 + bo[c]     + g_x1[o];
        g_x2[o + 1] = v1 + bo[c + 1] + g_x1[o + 1];
    }
};

struct Moe1Prob {
    const float* w1;
    const float* b1;
    DEV int K() const { return Dc; }
    DEV bool skip() const { return (int)(blockIdx.y * 128) >= g_cnt[blockIdx.z >> 1]; }
    DEV void loadA(float4 (&ra)[2], int m0, int k0, int tid, int z) const {
        int g = z >> 1;
        int i = m0 + (tid >> 1);
        if (i < g_cnt[g]) {
            int tok = g_perm[(g << 12) + i];
            const float* p = &g_x2[(size_t)tok * Dc + k0 + ((tid & 1) << 2)];
            ra[0] = *(const float4*)p;
            ra[1] = *(const float4*)(p + 8);
        } else {
            ra[0] = ra[1] = make_float4(0.f, 0.f, 0.f, 0.f);
        }
    }
    DEV void storeA(float* As, const float4 (&ra)[2], int tid) const { stsA(As, ra, tid); }
    DEV void loadB(float4 (&rb)[2], int n0, int k0, int tid, int z) const {
        ldB_dense128(rb, w1 + (size_t)z * Dc * FFc, FFc, n0, k0, tid);
    }
    DEV void storeB(float* Bs, const float4 (&rb)[2], int tid) const { stsB128(Bs, rb, tid); }
    DEV void store2(int idx, int c, float v0, float v1, int z) const {
        int g = z >> 1, e = z & 1;
        if (idx >= g_cnt[g]) return;
        int tok = g_perm[(g << 12) + idx];
        size_t o = (size_t)tok * (Ec * FFc) + (e << 11) + c;
        const float* bb = &b1[(size_t)z * FFc + c];
        g_hid[o]     = gelu_f(v0 + bb[0]);
        g_hid[o + 1] = gelu_f(v1 + bb[1]);
    }
};

struct Moe2Prob {
    const float* w2;
    const float* b2;
    float* out;
    DEV int K() const { return Ec * FFc; }
    DEV bool skip() const { return (int)(blockIdx.y * 128) >= g_cnt[blockIdx.z]; }
    DEV void loadA(float4 (&ra)[2], int m0, int k0, int tid, int z) const {
        int g = z;
        int i = m0 + (tid >> 1);
        if (i < g_cnt[g]) {
            int tok = g_perm[(g << 12) + i];
            const float* p = &g_hid[(size_t)tok * (Ec * FFc) + k0 + ((tid & 1) << 2)];
            ra[0] = *(const float4*)p;
            ra[1] = *(const float4*)(p + 8);
        } else {
            ra[0] = ra[1] = make_float4(0.f, 0.f, 0.f, 0.f);
        }
    }
    DEV void storeA(float* As, const float4 (&ra)[2], int tid) const { stsA(As, ra, tid); }
    DEV void loadB(float4 (&rb)[2], int n0, int k0, int tid, int z) const {
        ldB_dense128(rb, w2 + (size_t)z * Ec * FFc * Dc, Dc, n0, k0, tid);
    }
    DEV void storeB(float* Bs, const float4 (&rb)[2], int tid) const { stsB128(Bs, rb, tid); }
    DEV void store2(int idx, int c, float v0, float v1, int z) const {
        int g = z;
        if (idx >= g_cnt[g]) return;
        int tok = g_perm[(g << 12) + idx];
        size_t o = (size_t)tok * Dc + c;
        float bs0 = b2[(size_t)(g * 2) * Dc + c] + b2[(size_t)(g * 2 + 1) * Dc + c];
        float bs1 = b2[(size_t)(g * 2) * Dc + c + 1] + b2[(size_t)(g * 2 + 1) * Dc + c + 1];
        out[o]     = 0.5f * v0 + 0.5f * bs0 + g_x2[o];
        out[o + 1] = 0.5f * v1 + 0.5f * bs1 + g_x2[o + 1];
    }
};

// ================= launch =================
extern "C" void kernel_launch(void* const* d_in, const int* in_sizes, int n_in,
                              void* d_out, int out_size) {
    const float* x    = (const float*)d_in[0];
    const int*   gid  = (const int*)d_in[1];
    const float* ln1s = (const float*)d_in[2];
    const float* ln1b = (const float*)d_in[3];
    const float* ck   = (const float*)d_in[4];
    const float* cb   = (const float*)d_in[5];
    const float* ln2s = (const float*)d_in[6];
    const float* ln2b = (const float*)d_in[7];
    const float* wq   = (const float*)d_in[8];
    const float* bq   = (const float*)d_in[9];
    const float* wk   = (const float*)d_in[10];
    const float* bk   = (const float*)d_in[11];
    const float* wv   = (const float*)d_in[12];
    const float* bv   = (const float*)d_in[13];
    const float* wo   = (const float*)d_in[14];
    const float* bo   = (const float*)d_in[15];
    const float* w1   = (const float*)d_in[16];
    const float* b1   = (const float*)d_in[17];
    const float* w2   = (const float*)d_in[18];
    const float* b2   = (const float*)d_in[19];
    float* out = (float*)d_out;

    ln_kernel<0><<<Nc, 256>>>(x, ln1s, ln1b);
    {
        ConvProb p{ck, cb, x};
        gemm_mma<128, ConvProb><<<dim3(Dc / 128, Nc / 128, 1), 256>>>(p);
    }
    ln_kernel<1><<<Nc, 256>>>(x, ln2s, ln2b);
    {
        QKVProb p;
        p.w[0] = wq; p.w[1] = wk; p.w[2] = wv;
        p.b[0] = bq; p.b[1] = bk; p.b[2] = bv;
        gemm_mma<128, QKVProb><<<dim3(Dc / 128, Nc / 128, 3), 256>>>(p);
    }
    {
        ScoreProb p;
        gemm_mma<128, ScoreProb><<<dim3(Sc / 128, Sc / 128, Bc * Hc), 256>>>(p);
    }
    softmax_kernel<<<Bc * Hc * Sc, 256>>>();
    {
        AVProb p;
        gemm_mma<64, AVProb><<<dim3(1, Sc / 128, Bc * Hc), 256>>>(p);
    }
    {
        OutProb p{wo, bo};
        gemm_mma<128, OutProb><<<dim3(Dc / 128, Nc / 128, 1), 256>>>(p);
    }
    zero_cnt_kernel<<<1, 32>>>();
    scatter_kernel<<<Nc / 256, 256>>>(gid);
    {
        Moe1Prob p{w1, b1};
        gemm_mma<128, Moe1Prob><<<dim3(FFc / 128, Nc / 128, Gc * Ec), 256>>>(p);
    }
    {
        Moe2Prob p{w2, b2, out};
        gemm_mma<128, Moe2Prob><<<dim3(Dc / 128, Nc / 128, Gc), 256>>>(p);
    }
}

// round 3
// speedup vs baseline: 3.1953x; 1.1374x over previous
#include <cuda_runtime.h>
#include <math.h>
#include <stdint.h>
#include <stddef.h>

#define DEV __device__ __forceinline__

constexpr int Bc = 2, Sc = 2048, Dc = 512, Hc = 8, HDc = 64, KC = 31;
constexpr int FFc = 2048, Gc = 4, Ec = 2;
constexpr int Nc = Bc * Sc; // 4096 tokens

// ---------------- scratch ----------------
__device__ float g_h1[Nc * Dc];
__device__ float g_x1[Nc * Dc];
__device__ float g_h2[Nc * Dc];
__device__ float g_q[Nc * Dc];
__device__ float g_k[Nc * Dc];
__device__ float g_v[Nc * Dc];
__device__ float g_o[Nc * Dc];
__device__ float g_x2[Nc * Dc];
__device__ float g_hid[(size_t)Nc * Ec * FFc];          // 64 MB
__device__ int   g_perm[Gc * Nc];
__device__ int   g_cnt[Gc];

DEV float gelu_f(float x) {
    const float c0 = 0.7978845608028654f;
    float t = c0 * (x + 0.044715f * x * x * x);
    return 0.5f * x * (1.0f + tanhf(t));
}

DEV float cv_tf32(float x) {
    uint32_t r;
    asm("cvt.rna.tf32.f32 %0, %1;" : "=r"(r) : "f"(x));
    return __uint_as_float(r);
}
DEV uint32_t cv_tf32u(float x) {
    uint32_t r;
    asm("cvt.rna.tf32.f32 %0, %1;" : "=r"(r) : "f"(x));
    return r;
}

DEV void mma_tf32(float (&c)[4], const uint32_t (&a)[4], const uint32_t (&b)[2]) {
    asm volatile(
        "mma.sync.aligned.m16n8k8.row.col.f32.tf32.tf32.f32 "
        "{%0,%1,%2,%3},{%4,%5,%6,%7},{%8,%9},{%0,%1,%2,%3};\n"
        : "+f"(c[0]), "+f"(c[1]), "+f"(c[2]), "+f"(c[3])
        : "r"(a[0]), "r"(a[1]), "r"(a[2]), "r"(a[3]), "r"(b[0]), "r"(b[1]));
}

// ---------------- LayerNorm ----------------
template <int WHICH>
__global__ void ln_kernel(const float* __restrict__ xin,
                          const float* __restrict__ sc,
                          const float* __restrict__ bi) {
    const float* src = (WHICH == 0) ? xin : g_x1;
    float* dst = (WHICH == 0) ? g_h1 : g_h2;
    int row = blockIdx.x;
    const float* xr = src + (size_t)row * Dc;
    float* orow = dst + (size_t)row * Dc;
    int t = threadIdx.x;
    float a = xr[t], b = xr[t + 256];
    float s = a + b, sq = a * a + b * b;
    __shared__ float sh[16];
#pragma unroll
    for (int o = 16; o; o >>= 1) {
        s += __shfl_xor_sync(0xffffffffu, s, o);
        sq += __shfl_xor_sync(0xffffffffu, sq, o);
    }
    int w = t >> 5;
    if ((t & 31) == 0) { sh[w] = s; sh[8 + w] = sq; }
    __syncthreads();
    if (t == 0) {
        float ts = 0.f, tq = 0.f;
#pragma unroll
        for (int i = 0; i < 8; i++) { ts += sh[i]; tq += sh[8 + i]; }
        float mean = ts * (1.0f / Dc);
        float var = tq * (1.0f / Dc) - mean * mean;
        sh[0] = mean;
        sh[1] = rsqrtf(var + 1e-6f);
    }
    __syncthreads();
    float mean = sh[0], rstd = sh[1];
    orow[t]       = (a - mean) * rstd * sc[t] + bi[t];
    orow[t + 256] = (b - mean) * rstd * sc[t + 256] + bi[t + 256];
}

// ---------------- routing ----------------
__global__ void zero_cnt_kernel() {
    if (threadIdx.x < Gc) g_cnt[threadIdx.x] = 0;
}
__global__ void scatter_kernel(const int* __restrict__ gid) {
    int n = blockIdx.x * 256 + threadIdx.x;
    if (n < Nc) {
        int g = gid[n];
        int p = atomicAdd(&g_cnt[g], 1);
        g_perm[(g << 12) + p] = n;
    }
}

// ---------------- fused flash attention (tf32 MMA) ----------------
// grid: (Sc/128, B*H). 256 threads = 8 warps; warp w owns query rows [w*16, w*16+16).
// S-tile = 64 keys per iteration, 32 iterations.
__global__ __launch_bounds__(256) void flash_kernel() {
    __shared__ float Ks[64 * 72];   // [hd][s]  (B operand of QK^T)
    __shared__ float Vs[64 * 72];   // [s][hd]  (B operand of PV)
    const int tid = threadIdx.x, lane = tid & 31, warp = tid >> 5;
    const int g = lane >> 2, t4 = lane & 3;
    const int q0 = blockIdx.x * 128;
    const int z = blockIdx.y, b = z >> 3, h = z & 7;
    const float* Qp = g_q + (size_t)(b << 11) * Dc + (h << 6);
    const float* Kp = g_k + (size_t)(b << 11) * Dc + (h << 6);
    const float* Vp = g_v + (size_t)(b << 11) * Dc + (h << 6);

    const int r0 = q0 + warp * 16 + g;     // rows r0 and r0+8

    // Q fragments in registers, scale 1/8 folded in (exact in tf32)
    uint32_t qa[8][4];
#pragma unroll
    for (int kb = 0; kb < 8; kb++) {
        int c0 = kb * 8 + t4;
        qa[kb][0] = cv_tf32u(Qp[(size_t)r0 * Dc + c0] * 0.125f);
        qa[kb][1] = cv_tf32u(Qp[(size_t)(r0 + 8) * Dc + c0] * 0.125f);
        qa[kb][2] = cv_tf32u(Qp[(size_t)r0 * Dc + c0 + 4] * 0.125f);
        qa[kb][3] = cv_tf32u(Qp[(size_t)(r0 + 8) * Dc + c0 + 4] * 0.125f);
    }

    float m0v = -1e30f, m1v = -1e30f, l0 = 0.f, l1 = 0.f;
    float oacc[8][4];
#pragma unroll
    for (int j = 0; j < 8; j++)
#pragma unroll
        for (int q = 0; q < 4; q++) oacc[j][q] = 0.f;

    // tile loaders: each thread handles key-row sl, 16 consecutive hd cols
    const int sl = tid & 63, cb = (tid >> 6) << 4;
    float4 kf[4], vf[4];
#pragma unroll
    for (int i = 0; i < 4; i++) {
        kf[i] = *(const float4*)&Kp[(size_t)sl * Dc + cb + i * 4];
        vf[i] = *(const float4*)&Vp[(size_t)sl * Dc + cb + i * 4];
    }

    const float LOG2E = 1.4426950408889634f;

    for (int st = 0; st < 32; st++) {
        // stage current tile to smem (tf32-rounded)
#pragma unroll
        for (int i = 0; i < 4; i++) {
            int c = cb + i * 4;
            Ks[(c + 0) * 72 + sl] = cv_tf32(kf[i].x);
            Ks[(c + 1) * 72 + sl] = cv_tf32(kf[i].y);
            Ks[(c + 2) * 72 + sl] = cv_tf32(kf[i].z);
            Ks[(c + 3) * 72 + sl] = cv_tf32(kf[i].w);
            *(float4*)&Vs[sl * 72 + c] = make_float4(
                cv_tf32(vf[i].x), cv_tf32(vf[i].y), cv_tf32(vf[i].z), cv_tf32(vf[i].w));
        }
        __syncthreads();
        if (st + 1 < 32) {
            int s1 = (st + 1) * 64;
#pragma unroll
            for (int i = 0; i < 4; i++) {
                kf[i] = *(const float4*)&Kp[(size_t)(s1 + sl) * Dc + cb + i * 4];
                vf[i] = *(const float4*)&Vp[(size_t)(s1 + sl) * Dc + cb + i * 4];
            }
        }

        // S = Q K^T (rows: r0/r0+8; cols: 64 keys)
        float sc[8][4];
#pragma unroll
        for (int j = 0; j < 8; j++)
#pragma unroll
            for (int q = 0; q < 4; q++) sc[j][q] = 0.f;
#pragma unroll
        for (int kb = 0; kb < 8; kb++) {
#pragma unroll
            for (int j = 0; j < 8; j++) {
                uint32_t bfr[2];
                bfr[0] = __float_as_uint(Ks[(kb * 8 + t4) * 72 + j * 8 + g]);
                bfr[1] = __float_as_uint(Ks[(kb * 8 + t4 + 4) * 72 + j * 8 + g]);
                mma_tf32(sc[j], qa[kb], bfr);
            }
        }

        // online softmax
        float mx0 = m0v, mx1 = m1v;
#pragma unroll
        for (int j = 0; j < 8; j++) {
            mx0 = fmaxf(mx0, fmaxf(sc[j][0], sc[j][1]));
            mx1 = fmaxf(mx1, fmaxf(sc[j][2], sc[j][3]));
        }
        mx0 = fmaxf(mx0, __shfl_xor_sync(0xffffffffu, mx0, 1));
        mx0 = fmaxf(mx0, __shfl_xor_sync(0xffffffffu, mx0, 2));
        mx1 = fmaxf(mx1, __shfl_xor_sync(0xffffffffu, mx1, 1));
        mx1 = fmaxf(mx1, __shfl_xor_sync(0xffffffffu, mx1, 2));
        float al0 = exp2f((m0v - mx0) * LOG2E);
        float al1 = exp2f((m1v - mx1) * LOG2E);
        m0v = mx0; m1v = mx1;
        float s0 = 0.f, s1 = 0.f;
#pragma unroll
        for (int j = 0; j < 8; j++) {
            sc[j][0] = exp2f((sc[j][0] - mx0) * LOG2E);
            sc[j][1] = exp2f((sc[j][1] - mx0) * LOG2E);
            sc[j][2] = exp2f((sc[j][2] - mx1) * LOG2E);
            sc[j][3] = exp2f((sc[j][3] - mx1) * LOG2E);
            s0 += sc[j][0] + sc[j][1];
            s1 += sc[j][2] + sc[j][3];
        }
        s0 += __shfl_xor_sync(0xffffffffu, s0, 1);
        s0 += __shfl_xor_sync(0xffffffffu, s0, 2);
        s1 += __shfl_xor_sync(0xffffffffu, s1, 1);
        s1 += __shfl_xor_sync(0xffffffffu, s1, 2);
        l0 = l0 * al0 + s0;
        l1 = l1 * al1 + s1;
#pragma unroll
        for (int j = 0; j < 8; j++) {
            oacc[j][0] *= al0; oacc[j][1] *= al0;
            oacc[j][2] *= al1; oacc[j][3] *= al1;
        }

        // PV: re-lay P from C-frag layout to A-frag layout via intra-quad shuffles
        const int srcA = (lane & ~3) | (t4 >> 1);
        const int srcB = srcA + 2;
        const bool odd = (t4 & 1);
#pragma unroll
        for (int kb = 0; kb < 8; kb++) {
            float p00 = sc[kb][0], p01 = sc[kb][1];
            float p10 = sc[kb][2], p11 = sc[kb][3];
            float v00 = __shfl_sync(0xffffffffu, p00, srcA);
            float v01 = __shfl_sync(0xffffffffu, p01, srcA);
            float v10 = __shfl_sync(0xffffffffu, p00, srcB);
            float v11 = __shfl_sync(0xffffffffu, p01, srcB);
            float w00 = __shfl_sync(0xffffffffu, p10, srcA);
            float w01 = __shfl_sync(0xffffffffu, p11, srcA);
            float w10 = __shfl_sync(0xffffffffu, p10, srcB);
            float w11 = __shfl_sync(0xffffffffu, p11, srcB);
            uint32_t pa[4];
            pa[0] = cv_tf32u(odd ? v01 : v00);  // row g,   col kb*8+t4
            pa[1] = cv_tf32u(odd ? w01 : w00);  // row g+8, col kb*8+t4
            pa[2] = cv_tf32u(odd ? v11 : v10);  // row g,   col kb*8+t4+4
            pa[3] = cv_tf32u(odd ? w11 : w10);  // row g+8, col kb*8+t4+4
#pragma unroll
            for (int jo = 0; jo < 8; jo++) {
                uint32_t bfr[2];
                bfr[0] = __float_as_uint(Vs[(kb * 8 + t4) * 72 + jo * 8 + g]);
                bfr[1] = __float_as_uint(Vs[(kb * 8 + t4 + 4) * 72 + jo * 8 + g]);
                mma_tf32(oacc[jo], pa, bfr);
            }
        }
        __syncthreads();
    }

    // epilogue: divide by l, write g_o
    float inv0 = 1.0f / l0, inv1 = 1.0f / l1;
    size_t ro0 = ((size_t)(b << 11) + r0) * Dc + (h << 6);
    size_t ro1 = ro0 + (size_t)8 * Dc;
#pragma unroll
    for (int jo = 0; jo < 8; jo++) {
        int c = jo * 8 + 2 * t4;
        g_o[ro0 + c]     = oacc[jo][0] * inv0;
        g_o[ro0 + c + 1] = oacc[jo][1] * inv0;
        g_o[ro1 + c]     = oacc[jo][2] * inv1;
        g_o[ro1 + c + 1] = oacc[jo][3] * inv1;
    }
}

// ---------------- shared fill helpers ----------------
DEV void ldA_dense(float4 (&ra)[2], const float* __restrict__ base, size_t ld,
                   int m0, int k0, int tid) {
    int m = m0 + (tid >> 1), kb = k0 + ((tid & 1) << 2);
    const float* p = &base[(size_t)m * ld + kb];
    ra[0] = *(const float4*)p;
    ra[1] = *(const float4*)(p + 8);
}
DEV void stsA(float* As, const float4 (&ra)[2], int tid) {
    int m = tid >> 1, kb = (tid & 1) << 2;
    float* p = &As[m * 20 + kb];
    p[0] = cv_tf32(ra[0].x); p[1] = cv_tf32(ra[0].y);
    p[2] = cv_tf32(ra[0].z); p[3] = cv_tf32(ra[0].w);
    p[8] = cv_tf32(ra[1].x); p[9] = cv_tf32(ra[1].y);
    p[10] = cv_tf32(ra[1].z); p[11] = cv_tf32(ra[1].w);
}
DEV void ldB_dense128(float4 (&rb)[2], const float* __restrict__ base, size_t ld,
                      int n0, int k0, int tid) {
    int kk = k0 + (tid >> 4), c = n0 + ((tid & 15) << 3);
    const float* p = &base[(size_t)kk * ld + c];
    rb[0] = *(const float4*)p;
    rb[1] = *(const float4*)(p + 4);
}
DEV void stsB128(float* Bs, const float4 (&rb)[2], int tid) {
    int kk = tid >> 4, c = (tid & 15) << 3;
    float* p = &Bs[kk * 136 + c];
    p[0] = cv_tf32(rb[0].x); p[1] = cv_tf32(rb[0].y);
    p[2] = cv_tf32(rb[0].z); p[3] = cv_tf32(rb[0].w);
    p[4] = cv_tf32(rb[1].x); p[5] = cv_tf32(rb[1].y);
    p[6] = cv_tf32(rb[1].z); p[7] = cv_tf32(rb[1].w);
}

// ---------------- double-buffered MMA GEMM (M 128, N 128, K step 16) ----------------
template <int NT, class P>
__global__ __launch_bounds__(256, 2) void gemm_mma(P p) {
    if (p.skip()) return;
    constexpr int BSTR = NT + 8;
    constexpr int NF = NT / 32;
    __shared__ __align__(16) float As[2][128 * 20];
    __shared__ __align__(16) float Bs[2][16 * BSTR];
    int tid = threadIdx.x, lane = tid & 31, warp = tid >> 5;
    int m0 = blockIdx.y * 128, n0 = blockIdx.x * NT, z = blockIdx.z;
    int wm = warp >> 2, wn = warp & 3;
    int g = lane >> 2, t4 = lane & 3;

    float acc[4][NF][4];
#pragma unroll
    for (int i = 0; i < 4; i++)
#pragma unroll
        for (int j = 0; j < NF; j++)
#pragma unroll
            for (int q = 0; q < 4; q++) acc[i][j][q] = 0.f;

    float4 ra[2], rb[2];
    int Kt = p.K();
    p.loadA(ra, m0, 0, tid, z);
    p.loadB(rb, n0, 0, tid, z);
    p.storeA(As[0], ra, tid);
    p.storeB(Bs[0], rb, tid);
    __syncthreads();
    int cur = 0;

    for (int k0 = 0; k0 < Kt; k0 += 16) {
        bool has_next = (k0 + 16 < Kt);
        if (has_next) {
            p.loadA(ra, m0, k0 + 16, tid, z);
            p.loadB(rb, n0, k0 + 16, tid, z);
        }
#pragma unroll
        for (int kk = 0; kk < 16; kk += 8) {
            uint32_t a[4][4], bf[NF][2];
#pragma unroll
            for (int i = 0; i < 4; i++) {
                const float* ap = &As[cur][(wm * 64 + i * 16 + g) * 20 + kk + t4];
                a[i][0] = __float_as_uint(ap[0]);
                a[i][1] = __float_as_uint(ap[8 * 20]);
                a[i][2] = __float_as_uint(ap[4]);
                a[i][3] = __float_as_uint(ap[8 * 20 + 4]);
            }
#pragma unroll
            for (int j = 0; j < NF; j++) {
                const float* bp = &Bs[cur][(kk + t4) * BSTR + wn * (NT / 4) + j * 8 + g];
                bf[j][0] = __float_as_uint(bp[0]);
                bf[j][1] = __float_as_uint(bp[4 * BSTR]);
            }
#pragma unroll
            for (int i = 0; i < 4; i++)
#pragma unroll
                for (int j = 0; j < NF; j++) mma_tf32(acc[i][j], a[i], bf[j]);
        }
        if (has_next) {
            p.storeA(As[cur ^ 1], ra, tid);
            p.storeB(Bs[cur ^ 1], rb, tid);
            __syncthreads();
            cur ^= 1;
        }
    }
#pragma unroll
    for (int i = 0; i < 4; i++) {
        int r0 = m0 + wm * 64 + i * 16 + g;
#pragma unroll
        for (int j = 0; j < NF; j++) {
            int c = n0 + wn * (NT / 4) + j * 8 + 2 * t4;
            p.store2(r0, c, acc[i][j][0], acc[i][j][1], z);
            p.store2(r0 + 8, c, acc[i][j][2], acc[i][j][3], z);
        }
    }
}

// ================= functors =================

struct ConvProb {
    const float* ck;
    const float* cb;
    const float* xres;
    DEV int K() const { return KC * Dc; }
    DEV bool skip() const { return false; }
    DEV void loadA(float4 (&ra)[2], int m0, int k0, int tid, int) const {
        int m = m0 + (tid >> 1);
        int b = m >> 11, s = m & 2047;
        int k = k0 + ((tid & 1) << 2);
        int kk = k >> 9, ci = k & 511;
        int sr = s + kk - 15;
        if ((unsigned)sr < (unsigned)Sc) {
            const float* p = &g_h1[(size_t)((b << 11) + sr) * Dc + ci];
            ra[0] = *(const float4*)p;
            ra[1] = *(const float4*)(p + 8);
        } else {
            ra[0] = ra[1] = make_float4(0.f, 0.f, 0.f, 0.f);
        }
    }
    DEV void storeA(float* As, const float4 (&ra)[2], int tid) const { stsA(As, ra, tid); }
    DEV void loadB(float4 (&rb)[2], int n0, int k0, int tid, int) const {
        ldB_dense128(rb, ck, Dc, n0, k0, tid);
    }
    DEV void storeB(float* Bs, const float4 (&rb)[2], int tid) const { stsB128(Bs, rb, tid); }
    DEV void store2(int m, int c, float v0, float v1, int) const {
        size_t o = (size_t)m * Dc + c;
        g_x1[o]     = gelu_f(v0 + cb[c])     + xres[o];
        g_x1[o + 1] = gelu_f(v1 + cb[c + 1]) + xres[o + 1];
    }
};

struct QKVProb {
    const float* w[3];
    const float* b[3];
    DEV int K() const { return Dc; }
    DEV bool skip() const { return false; }
    DEV void loadA(float4 (&ra)[2], int m0, int k0, int tid, int) const {
        ldA_dense(ra, g_h2, Dc, m0, k0, tid);
    }
    DEV void storeA(float* As, const float4 (&ra)[2], int tid) const { stsA(As, ra, tid); }
    DEV void loadB(float4 (&rb)[2], int n0, int k0, int tid, int z) const {
        ldB_dense128(rb, w[z], Dc, n0, k0, tid);
    }
    DEV void storeB(float* Bs, const float4 (&rb)[2], int tid) const { stsB128(Bs, rb, tid); }
    DEV void store2(int m, int c, float v0, float v1, int z) const {
        float* outs[3] = {g_q, g_k, g_v};
        float* o = outs[z];
        const float* bias = b[z];
        size_t off = (size_t)m * Dc + c;
        o[off] = v0 + bias[c];
        o[off + 1] = v1 + bias[c + 1];
    }
};

struct OutProb {
    const float* wo;
    const float* bo;
    DEV int K() const { return Dc; }
    DEV bool skip() const { return false; }
    DEV void loadA(float4 (&ra)[2], int m0, int k0, int tid, int) const {
        ldA_dense(ra, g_o, Dc, m0, k0, tid);
    }
    DEV void storeA(float* As, const float4 (&ra)[2], int tid) const { stsA(As, ra, tid); }
    DEV void loadB(float4 (&rb)[2], int n0, int k0, int tid, int) const {
        ldB_dense128(rb, wo, Dc, n0, k0, tid);
    }
    DEV void storeB(float* Bs, const float4 (&rb)[2], int tid) const { stsB128(Bs, rb, tid); }
    DEV void store2(int m, int c, float v0, float v1, int) const {
        size_t o = (size_t)m * Dc + c;
        g_x2[o]     = v0 + bo[c]     + g_x1[o];
        g_x2[o + 1] = v1 + bo[c + 1] + g_x1[o + 1];
    }
};

struct Moe1Prob {
    const float* w1;
    const float* b1;
    DEV int K() const { return Dc; }
    DEV bool skip() const { return (int)(blockIdx.y * 128) >= g_cnt[blockIdx.z >> 1]; }
    DEV void loadA(float4 (&ra)[2], int m0, int k0, int tid, int z) const {
        int g = z >> 1;
        int i = m0 + (tid >> 1);
        if (i < g_cnt[g]) {
            int tok = g_perm[(g << 12) + i];
            const float* p = &g_x2[(size_t)tok * Dc + k0 + ((tid & 1) << 2)];
            ra[0] = *(const float4*)p;
            ra[1] = *(const float4*)(p + 8);
        } else {
            ra[0] = ra[1] = make_float4(0.f, 0.f, 0.f, 0.f);
        }
    }
    DEV void storeA(float* As, const float4 (&ra)[2], int tid) const { stsA(As, ra, tid); }
    DEV void loadB(float4 (&rb)[2], int n0, int k0, int tid, int z) const {
        ldB_dense128(rb, w1 + (size_t)z * Dc * FFc, FFc, n0, k0, tid);
    }
    DEV void storeB(float* Bs, const float4 (&rb)[2], int tid) const { stsB128(Bs, rb, tid); }
    DEV void store2(int idx, int c, float v0, float v1, int z) const {
        int g = z >> 1, e = z & 1;
        if (idx >= g_cnt[g]) return;
        int tok = g_perm[(g << 12) + idx];
        size_t o = (size_t)tok * (Ec * FFc) + (e << 11) + c;
        const float* bb = &b1[(size_t)z * FFc + c];
        g_hid[o]     = gelu_f(v0 + bb[0]);
        g_hid[o + 1] = gelu_f(v1 + bb[1]);
    }
};

struct Moe2Prob {
    const float* w2;
    const float* b2;
    float* out;
    DEV int K() const { return Ec * FFc; }
    DEV bool skip() const { return (int)(blockIdx.y * 128) >= g_cnt[blockIdx.z]; }
    DEV void loadA(float4 (&ra)[2], int m0, int k0, int tid, int z) const {
        int g = z;
        int i = m0 + (tid >> 1);
        if (i < g_cnt[g]) {
            int tok = g_perm[(g << 12) + i];
            const float* p = &g_hid[(size_t)tok * (Ec * FFc) + k0 + ((tid & 1) << 2)];
            ra[0] = *(const float4*)p;
            ra[1] = *(const float4*)(p + 8);
        } else {
            ra[0] = ra[1] = make_float4(0.f, 0.f, 0.f, 0.f);
        }
    }
    DEV void storeA(float* As, const float4 (&ra)[2], int tid) const { stsA(As, ra, tid); }
    DEV void loadB(float4 (&rb)[2], int n0, int k0, int tid, int z) const {
        ldB_dense128(rb, w2 + (size_t)z * Ec * FFc * Dc, Dc, n0, k0, tid);
    }
    DEV void storeB(float* Bs, const float4 (&rb)[2], int tid) const { stsB128(Bs, rb, tid); }
    DEV void store2(int idx, int c, float v0, float v1, int z) const {
        int g = z;
        if (idx >= g_cnt[g]) return;
        int tok = g_perm[(g << 12) + idx];
        size_t o = (size_t)tok * Dc + c;
        float bs0 = b2[(size_t)(g * 2) * Dc + c] + b2[(size_t)(g * 2 + 1) * Dc + c];
        float bs1 = b2[(size_t)(g * 2) * Dc + c + 1] + b2[(size_t)(g * 2 + 1) * Dc + c + 1];
        out[o]     = 0.5f * v0 + 0.5f * bs0 + g_x2[o];
        out[o + 1] = 0.5f * v1 + 0.5f * bs1 + g_x2[o + 1];
    }
};

// ================= launch =================
extern "C" void kernel_launch(void* const* d_in, const int* in_sizes, int n_in,
                              void* d_out, int out_size) {
    const float* x    = (const float*)d_in[0];
    const int*   gid  = (const int*)d_in[1];
    const float* ln1s = (const float*)d_in[2];
    const float* ln1b = (const float*)d_in[3];
    const float* ck   = (const float*)d_in[4];
    const float* cb   = (const float*)d_in[5];
    const float* ln2s = (const float*)d_in[6];
    const float* ln2b = (const float*)d_in[7];
    const float* wq   = (const float*)d_in[8];
    const float* bq   = (const float*)d_in[9];
    const float* wk   = (const float*)d_in[10];
    const float* bk   = (const float*)d_in[11];
    const float* wv   = (const float*)d_in[12];
    const float* bv   = (const float*)d_in[13];
    const float* wo   = (const float*)d_in[14];
    const float* bo   = (const float*)d_in[15];
    const float* w1   = (const float*)d_in[16];
    const float* b1   = (const float*)d_in[17];
    const float* w2   = (const float*)d_in[18];
    const float* b2   = (const float*)d_in[19];
    float* out = (float*)d_out;

    ln_kernel<0><<<Nc, 256>>>(x, ln1s, ln1b);
    {
        ConvProb p{ck, cb, x};
        gemm_mma<128, ConvProb><<<dim3(Dc / 128, Nc / 128, 1), 256>>>(p);
    }
    ln_kernel<1><<<Nc, 256>>>(x, ln2s, ln2b);
    {
        QKVProb p;
        p.w[0] = wq; p.w[1] = wk; p.w[2] = wv;
        p.b[0] = bq; p.b[1] = bk; p.b[2] = bv;
        gemm_mma<128, QKVProb><<<dim3(Dc / 128, Nc / 128, 3), 256>>>(p);
    }
    flash_kernel<<<dim3(Sc / 128, Bc * Hc), 256>>>();
    {
        OutProb p{wo, bo};
        gemm_mma<128, OutProb><<<dim3(Dc / 128, Nc / 128, 1), 256>>>(p);
    }
    zero_cnt_kernel<<<1, 32>>>();
    scatter_kernel<<<Nc / 256, 256>>>(gid);
    {
        Moe1Prob p{w1, b1};
        gemm_mma<128, Moe1Prob><<<dim3(FFc / 128, Nc / 128, Gc * Ec), 256>>>(p);
    }
    {
        Moe2Prob p{w2, b2, out};
        gemm_mma<128, Moe2Prob><<<dim3(Dc / 128, Nc / 128, Gc), 256>>>(p);
    }
}

// round 4
// speedup vs baseline: 3.5653x; 1.1158x over previous
#include <cuda_runtime.h>
#include <math.h>
#include <stdint.h>
#include <stddef.h>

#define DEV __device__ __forceinline__

constexpr int Bc = 2, Sc = 2048, Dc = 512, Hc = 8, HDc = 64, KC = 31;
constexpr int FFc = 2048, Gc = 4, Ec = 2;
constexpr int Nc = Bc * Sc; // 4096 tokens

// ---------------- scratch ----------------
__device__ float g_h1[Nc * Dc];
__device__ float g_x1[Nc * Dc];
__device__ float g_h2[Nc * Dc];
__device__ float g_q[Nc * Dc];
__device__ float g_k[Nc * Dc];
__device__ float g_v[Nc * Dc];
__device__ float g_o[Nc * Dc];
__device__ float g_x2[Nc * Dc];
__device__ float g_hid[(size_t)Nc * Ec * FFc];
__device__ int   g_perm[Gc * Nc];
__device__ int   g_cnt[Gc];

DEV float gelu_f(float x) {
    const float c0 = 0.7978845608028654f;
    float t = c0 * (x + 0.044715f * x * x * x);
    return 0.5f * x * (1.0f + tanhf(t));
}

DEV void mma_tf32(float (&c)[4], const uint32_t (&a)[4], const uint32_t (&b)[2]) {
    asm volatile(
        "mma.sync.aligned.m16n8k8.row.col.f32.tf32.tf32.f32 "
        "{%0,%1,%2,%3},{%4,%5,%6,%7},{%8,%9},{%0,%1,%2,%3};\n"
        : "+f"(c[0]), "+f"(c[1]), "+f"(c[2]), "+f"(c[3])
        : "r"(a[0]), "r"(a[1]), "r"(a[2]), "r"(a[3]), "r"(b[0]), "r"(b[1]));
}

// ---------------- cp.async helpers ----------------
DEV void cp16(uint32_t dst, const void* src) {
    asm volatile("cp.async.cg.shared.global [%0], [%1], 16;\n" :: "r"(dst), "l"(src));
}
DEV void cp16z(uint32_t dst, const void* src, bool pred) {
    int sz = pred ? 16 : 0;
    asm volatile("cp.async.cg.shared.global [%0], [%1], 16, %2;\n"
                 :: "r"(dst), "l"(src), "r"(sz));
}
DEV void cp_commit() { asm volatile("cp.async.commit_group;\n"); }
template <int N> DEV void cp_wait() { asm volatile("cp.async.wait_group %0;\n" :: "n"(N)); }

// ---------------- LayerNorm ----------------
template <int WHICH>
__global__ void ln_kernel(const float* __restrict__ xin,
                          const float* __restrict__ sc,
                          const float* __restrict__ bi) {
    const float* src = (WHICH == 0) ? xin : g_x1;
    float* dst = (WHICH == 0) ? g_h1 : g_h2;
    int row = blockIdx.x;
    const float* xr = src + (size_t)row * Dc;
    float* orow = dst + (size_t)row * Dc;
    int t = threadIdx.x;
    float a = xr[t], b = xr[t + 256];
    float s = a + b, sq = a * a + b * b;
    __shared__ float sh[16];
#pragma unroll
    for (int o = 16; o; o >>= 1) {
        s += __shfl_xor_sync(0xffffffffu, s, o);
        sq += __shfl_xor_sync(0xffffffffu, sq, o);
    }
    int w = t >> 5;
    if ((t & 31) == 0) { sh[w] = s; sh[8 + w] = sq; }
    __syncthreads();
    if (t == 0) {
        float ts = 0.f, tq = 0.f;
#pragma unroll
        for (int i = 0; i < 8; i++) { ts += sh[i]; tq += sh[8 + i]; }
        float mean = ts * (1.0f / Dc);
        float var = tq * (1.0f / Dc) - mean * mean;
        sh[0] = mean;
        sh[1] = rsqrtf(var + 1e-6f);
    }
    __syncthreads();
    float mean = sh[0], rstd = sh[1];
    orow[t]       = (a - mean) * rstd * sc[t] + bi[t];
    orow[t + 256] = (b - mean) * rstd * sc[t + 256] + bi[t + 256];
}

// ---------------- routing ----------------
__global__ void zero_cnt_kernel() {
    if (threadIdx.x < Gc) g_cnt[threadIdx.x] = 0;
}
__global__ void scatter_kernel(const int* __restrict__ gid) {
    int n = blockIdx.x * 256 + threadIdx.x;
    if (n < Nc) {
        int g = gid[n];
        int p = atomicAdd(&g_cnt[g], 1);
        g_perm[(g << 12) + p] = n;
    }
}

// ---------------- fused flash attention (tf32 MMA, cp.async double buffer) ----------------
// K/V tiles stored [s][hd], stride 68 floats (conflict-free for both read patterns).
constexpr int FKSZ = 64 * 68; // floats per K (or V) stage
__global__ __launch_bounds__(256) void flash_kernel() {
    extern __shared__ float fsm[];
    float* Ksm = fsm;               // [2][FKSZ]
    float* Vsm = fsm + 2 * FKSZ;    // [2][FKSZ]
    uint32_t kbase = (uint32_t)__cvta_generic_to_shared(Ksm);
    uint32_t vbase = (uint32_t)__cvta_generic_to_shared(Vsm);

    const int tid = threadIdx.x, lane = tid & 31, warp = tid >> 5;
    const int g = lane >> 2, t4 = lane & 3;
    const int q0 = blockIdx.x * 128;
    const int z = blockIdx.y, b = z >> 3, h = z & 7;
    const float* Qp = g_q + (size_t)(b << 11) * Dc + (h << 6);
    const float* Kp = g_k + (size_t)(b << 11) * Dc + (h << 6);
    const float* Vp = g_v + (size_t)(b << 11) * Dc + (h << 6);

    const int r0 = q0 + warp * 16 + g;

    // Q fragments (raw fp32 * 0.125; MMA truncates to tf32)
    uint32_t qa[8][4];
#pragma unroll
    for (int kb = 0; kb < 8; kb++) {
        int c0 = kb * 8 + t4;
        qa[kb][0] = __float_as_uint(Qp[(size_t)r0 * Dc + c0] * 0.125f);
        qa[kb][1] = __float_as_uint(Qp[(size_t)(r0 + 8) * Dc + c0] * 0.125f);
        qa[kb][2] = __float_as_uint(Qp[(size_t)r0 * Dc + c0 + 4] * 0.125f);
        qa[kb][3] = __float_as_uint(Qp[(size_t)(r0 + 8) * Dc + c0 + 4] * 0.125f);
    }

    float m0v = -1e30f, m1v = -1e30f, l0 = 0.f, l1 = 0.f;
    float oacc[8][4];
#pragma unroll
    for (int j = 0; j < 8; j++)
#pragma unroll
        for (int q = 0; q < 4; q++) oacc[j][q] = 0.f;

    const int sl = tid & 63, cbf = (tid >> 6) << 4;

    auto issueKV = [&](int st, int slot) {
        const float* kp = &Kp[(size_t)(st * 64 + sl) * Dc + cbf];
        const float* vp = &Vp[(size_t)(st * 64 + sl) * Dc + cbf];
        uint32_t kd = kbase + (uint32_t)((slot * FKSZ + sl * 68 + cbf) << 2);
        uint32_t vd = vbase + (uint32_t)((slot * FKSZ + sl * 68 + cbf) << 2);
#pragma unroll
        for (int i = 0; i < 4; i++) {
            cp16(kd + i * 16, kp + i * 4);
            cp16(vd + i * 16, vp + i * 4);
        }
    };

    issueKV(0, 0);
    cp_commit();

    const float LOG2E = 1.4426950408889634f;

    for (int st = 0; st < 32; st++) {
        cp_wait<0>();
        __syncthreads();
        if (st + 1 < 32) issueKV(st + 1, (st + 1) & 1);
        cp_commit();

        const float* Ks = Ksm + (st & 1) * FKSZ;
        const float* Vs = Vsm + (st & 1) * FKSZ;

        // S = Q K^T
        float sc[8][4];
#pragma unroll
        for (int j = 0; j < 8; j++)
#pragma unroll
            for (int q = 0; q < 4; q++) sc[j][q] = 0.f;
#pragma unroll
        for (int kb = 0; kb < 8; kb++) {
#pragma unroll
            for (int j = 0; j < 8; j++) {
                uint32_t bfr[2];
                bfr[0] = __float_as_uint(Ks[(j * 8 + g) * 68 + kb * 8 + t4]);
                bfr[1] = __float_as_uint(Ks[(j * 8 + g) * 68 + kb * 8 + t4 + 4]);
                mma_tf32(sc[j], qa[kb], bfr);
            }
        }

        // online softmax
        float mx0 = m0v, mx1 = m1v;
#pragma unroll
        for (int j = 0; j < 8; j++) {
            mx0 = fmaxf(mx0, fmaxf(sc[j][0], sc[j][1]));
            mx1 = fmaxf(mx1, fmaxf(sc[j][2], sc[j][3]));
        }
        mx0 = fmaxf(mx0, __shfl_xor_sync(0xffffffffu, mx0, 1));
        mx0 = fmaxf(mx0, __shfl_xor_sync(0xffffffffu, mx0, 2));
        mx1 = fmaxf(mx1, __shfl_xor_sync(0xffffffffu, mx1, 1));
        mx1 = fmaxf(mx1, __shfl_xor_sync(0xffffffffu, mx1, 2));
        float al0 = exp2f((m0v - mx0) * LOG2E);
        float al1 = exp2f((m1v - mx1) * LOG2E);
        m0v = mx0; m1v = mx1;
        float s0 = 0.f, s1 = 0.f;
#pragma unroll
        for (int j = 0; j < 8; j++) {
            sc[j][0] = exp2f((sc[j][0] - mx0) * LOG2E);
            sc[j][1] = exp2f((sc[j][1] - mx0) * LOG2E);
            sc[j][2] = exp2f((sc[j][2] - mx1) * LOG2E);
            sc[j][3] = exp2f((sc[j][3] - mx1) * LOG2E);
            s0 += sc[j][0] + sc[j][1];
            s1 += sc[j][2] + sc[j][3];
        }
        s0 += __shfl_xor_sync(0xffffffffu, s0, 1);
        s0 += __shfl_xor_sync(0xffffffffu, s0, 2);
        s1 += __shfl_xor_sync(0xffffffffu, s1, 1);
        s1 += __shfl_xor_sync(0xffffffffu, s1, 2);
        l0 = l0 * al0 + s0;
        l1 = l1 * al1 + s1;
#pragma unroll
        for (int j = 0; j < 8; j++) {
            oacc[j][0] *= al0; oacc[j][1] *= al0;
            oacc[j][2] *= al1; oacc[j][3] *= al1;
        }

        // PV: C-frag -> A-frag via intra-quad shuffles
        const int srcA = (lane & ~3) | (t4 >> 1);
        const int srcB = srcA + 2;
        const bool odd = (t4 & 1);
#pragma unroll
        for (int kb = 0; kb < 8; kb++) {
            float p00 = sc[kb][0], p01 = sc[kb][1];
            float p10 = sc[kb][2], p11 = sc[kb][3];
            float v00 = __shfl_sync(0xffffffffu, p00, srcA);
            float v01 = __shfl_sync(0xffffffffu, p01, srcA);
            float v10 = __shfl_sync(0xffffffffu, p00, srcB);
            float v11 = __shfl_sync(0xffffffffu, p01, srcB);
            float w00 = __shfl_sync(0xffffffffu, p10, srcA);
            float w01 = __shfl_sync(0xffffffffu, p11, srcA);
            float w10 = __shfl_sync(0xffffffffu, p10, srcB);
            float w11 = __shfl_sync(0xffffffffu, p11, srcB);
            uint32_t pa[4];
            pa[0] = __float_as_uint(odd ? v01 : v00);
            pa[1] = __float_as_uint(odd ? w01 : w00);
            pa[2] = __float_as_uint(odd ? v11 : v10);
            pa[3] = __float_as_uint(odd ? w11 : w10);
#pragma unroll
            for (int jo = 0; jo < 8; jo++) {
                uint32_t bfr[2];
                bfr[0] = __float_as_uint(Vs[(kb * 8 + t4) * 68 + jo * 8 + g]);
                bfr[1] = __float_as_uint(Vs[(kb * 8 + t4 + 4) * 68 + jo * 8 + g]);
                mma_tf32(oacc[jo], pa, bfr);
            }
        }
        __syncthreads();
    }

    float inv0 = 1.0f / l0, inv1 = 1.0f / l1;
    size_t ro0 = ((size_t)(b << 11) + r0) * Dc + (h << 6);
    size_t ro1 = ro0 + (size_t)8 * Dc;
#pragma unroll
    for (int jo = 0; jo < 8; jo++) {
        int c = jo * 8 + 2 * t4;
        g_o[ro0 + c]     = oacc[jo][0] * inv0;
        g_o[ro0 + c + 1] = oacc[jo][1] * inv0;
        g_o[ro1 + c]     = oacc[jo][2] * inv1;
        g_o[ro1 + c + 1] = oacc[jo][3] * inv1;
    }
}

// ---------------- cp.async tile-fill helpers ----------------
// A stage: [128][20] floats ; B stage: [16][136] floats
constexpr int ASZ = 128 * 20;   // 2560 floats
constexpr int BSZ = 16 * 136;   // 2176 floats
constexpr int GSTAGES = 3;

DEV void cpA_dense(uint32_t dst, const float* __restrict__ base, size_t ld,
                   int m0, int k0, int tid) {
    int mr = tid >> 1, kb = (tid & 1) << 2;
    const float* src = &base[(size_t)(m0 + mr) * ld + k0 + kb];
    uint32_t d = dst + (uint32_t)((mr * 20 + kb) << 2);
    cp16(d, src);
    cp16(d + 32, src + 8);
}
DEV void cpB_dense(uint32_t dst, const float* __restrict__ base, size_t ld,
                   int n0, int k0, int tid) {
    int kk = tid >> 4, c = (tid & 15) << 3;
    const float* src = &base[(size_t)(k0 + kk) * ld + n0 + c];
    uint32_t d = dst + (uint32_t)((kk * 136 + c) << 2);
    cp16(d, src);
    cp16(d + 16, src + 4);
}

// ---------------- 3-stage pipelined MMA GEMM (128x128, k-step 16) ----------------
template <class P>
__global__ __launch_bounds__(256, 2) void gemm_mma(P p) {
    if (p.skip()) return;
    extern __shared__ float sm[];
    float* As = sm;
    float* Bs = sm + GSTAGES * ASZ;
    uint32_t abase = (uint32_t)__cvta_generic_to_shared(As);
    uint32_t bbase = (uint32_t)__cvta_generic_to_shared(Bs);

    int tid = threadIdx.x, lane = tid & 31, warp = tid >> 5;
    int m0 = blockIdx.y * 128, n0 = blockIdx.x * 128, z = blockIdx.z;
    int wm = warp >> 2, wn = warp & 3;
    int g = lane >> 2, t4 = lane & 3;

    float acc[4][4][4];
#pragma unroll
    for (int i = 0; i < 4; i++)
#pragma unroll
        for (int j = 0; j < 4; j++)
#pragma unroll
            for (int q = 0; q < 4; q++) acc[i][j][q] = 0.f;

    int T = p.K() >> 4;

#pragma unroll
    for (int s = 0; s < GSTAGES - 1; s++) {
        p.cpA(abase + (uint32_t)(s * ASZ * 4), m0, s * 16, tid, z);
        p.cpB(bbase + (uint32_t)(s * BSZ * 4), n0, s * 16, tid, z);
        cp_commit();
    }

    for (int t = 0; t < T; t++) {
        cp_wait<GSTAGES - 2>();
        __syncthreads();
        int nf = t + GSTAGES - 1;
        if (nf < T) {
            int slo = nf % GSTAGES;
            p.cpA(abase + (uint32_t)(slo * ASZ * 4), m0, nf * 16, tid, z);
            p.cpB(bbase + (uint32_t)(slo * BSZ * 4), n0, nf * 16, tid, z);
        }
        cp_commit();

        const float* Ac = As + (t % GSTAGES) * ASZ;
        const float* Bcur = Bs + (t % GSTAGES) * BSZ;
#pragma unroll
        for (int kk = 0; kk < 16; kk += 8) {
            uint32_t a[4][4], bf[4][2];
#pragma unroll
            for (int i = 0; i < 4; i++) {
                const float* ap = &Ac[(wm * 64 + i * 16 + g) * 20 + kk + t4];
                a[i][0] = __float_as_uint(ap[0]);
                a[i][1] = __float_as_uint(ap[8 * 20]);
                a[i][2] = __float_as_uint(ap[4]);
                a[i][3] = __float_as_uint(ap[8 * 20 + 4]);
            }
#pragma unroll
            for (int j = 0; j < 4; j++) {
                const float* bp = &Bcur[(kk + t4) * 136 + wn * 32 + j * 8 + g];
                bf[j][0] = __float_as_uint(bp[0]);
                bf[j][1] = __float_as_uint(bp[4 * 136]);
            }
#pragma unroll
            for (int i = 0; i < 4; i++)
#pragma unroll
                for (int j = 0; j < 4; j++) mma_tf32(acc[i][j], a[i], bf[j]);
        }
    }
#pragma unroll
    for (int i = 0; i < 4; i++) {
        int r0 = m0 + wm * 64 + i * 16 + g;
#pragma unroll
        for (int j = 0; j < 4; j++) {
            int c = n0 + wn * 32 + j * 8 + 2 * t4;
            p.store2(r0, c, acc[i][j][0], acc[i][j][1], z);
            p.store2(r0 + 8, c, acc[i][j][2], acc[i][j][3], z);
        }
    }
}

// ================= functors =================

struct ConvProb {
    const float* ck;
    const float* cb;
    const float* xres;
    DEV int K() const { return KC * Dc; }
    DEV bool skip() const { return false; }
    DEV void cpA(uint32_t dst, int m0, int k0, int tid, int) const {
        int mr = tid >> 1;
        int m = m0 + mr;
        int b = m >> 11, s = m & 2047;
        int kb = (tid & 1) << 2;
        int k = k0 + kb;
        int kk = k >> 9, ci = k & 511;     // 16-chunk never crosses a tap (512 % 16 == 0)
        int sr = s + kk - 15;
        bool ok = (unsigned)sr < (unsigned)Sc;
        int srs = ok ? sr : 0;
        const float* src = &g_h1[(size_t)((b << 11) + srs) * Dc + ci];
        uint32_t d = dst + (uint32_t)((mr * 20 + kb) << 2);
        cp16z(d, src, ok);
        cp16z(d + 32, src + 8, ok);
    }
    DEV void cpB(uint32_t dst, int n0, int k0, int tid, int) const {
        cpB_dense(dst, ck, Dc, n0, k0, tid);
    }
    DEV void store2(int m, int c, float v0, float v1, int) const {
        size_t o = (size_t)m * Dc + c;
        g_x1[o]     = gelu_f(v0 + cb[c])     + xres[o];
        g_x1[o + 1] = gelu_f(v1 + cb[c + 1]) + xres[o + 1];
    }
};

struct QKVProb {
    const float* w[3];
    const float* b[3];
    DEV int K() const { return Dc; }
    DEV bool skip() const { return false; }
    DEV void cpA(uint32_t dst, int m0, int k0, int tid, int) const {
        cpA_dense(dst, g_h2, Dc, m0, k0, tid);
    }
    DEV void cpB(uint32_t dst, int n0, int k0, int tid, int z) const {
        cpB_dense(dst, w[z], Dc, n0, k0, tid);
    }
    DEV void store2(int m, int c, float v0, float v1, int z) const {
        float* outs[3] = {g_q, g_k, g_v};
        float* o = outs[z];
        const float* bias = b[z];
        size_t off = (size_t)m * Dc + c;
        o[off] = v0 + bias[c];
        o[off + 1] = v1 + bias[c + 1];
    }
};

struct OutProb {
    const float* wo;
    const float* bo;
    DEV int K() const { return Dc; }
    DEV bool skip() const { return false; }
    DEV void cpA(uint32_t dst, int m0, int k0, int tid, int) const {
        cpA_dense(dst, g_o, Dc, m0, k0, tid);
    }
    DEV void cpB(uint32_t dst, int n0, int k0, int tid, int) const {
        cpB_dense(dst, wo, Dc, n0, k0, tid);
    }
    DEV void store2(int m, int c, float v0, float v1, int) const {
        size_t o = (size_t)m * Dc + c;
        g_x2[o]     = v0 + bo[c]     + g_x1[o];
        g_x2[o + 1] = v1 + bo[c + 1] + g_x1[o + 1];
    }
};

struct Moe1Prob {
    const float* w1;
    const float* b1;
    DEV int K() const { return Dc; }
    DEV bool skip() const { return (int)(blockIdx.y * 128) >= g_cnt[blockIdx.z >> 1]; }
    DEV void cpA(uint32_t dst, int m0, int k0, int tid, int z) const {
        int g = z >> 1;
        int mr = tid >> 1;
        int i = m0 + mr;
        bool ok = i < g_cnt[g];
        int tok = ok ? g_perm[(g << 12) + i] : 0;
        int kb = (tid & 1) << 2;
        const float* src = &g_x2[(size_t)tok * Dc + k0 + kb];
        uint32_t d = dst + (uint32_t)((mr * 20 + kb) << 2);
        cp16z(d, src, ok);
        cp16z(d + 32, src + 8, ok);
    }
    DEV void cpB(uint32_t dst, int n0, int k0, int tid, int z) const {
        cpB_dense(dst, w1 + (size_t)z * Dc * FFc, FFc, n0, k0, tid);
    }
    DEV void store2(int idx, int c, float v0, float v1, int z) const {
        int g = z >> 1, e = z & 1;
        if (idx >= g_cnt[g]) return;
        int tok = g_perm[(g << 12) + idx];
        size_t o = (size_t)tok * (Ec * FFc) + (e << 11) + c;
        const float* bb = &b1[(size_t)z * FFc + c];
        g_hid[o]     = gelu_f(v0 + bb[0]);
        g_hid[o + 1] = gelu_f(v1 + bb[1]);
    }
};

struct Moe2Prob {
    const float* w2;
    const float* b2;
    float* out;
    DEV int K() const { return Ec * FFc; }
    DEV bool skip() const { return (int)(blockIdx.y * 128) >= g_cnt[blockIdx.z]; }
    DEV void cpA(uint32_t dst, int m0, int k0, int tid, int z) const {
        int g = z;
        int mr = tid >> 1;
        int i = m0 + mr;
        bool ok = i < g_cnt[g];
        int tok = ok ? g_perm[(g << 12) + i] : 0;
        int kb = (tid & 1) << 2;
        const float* src = &g_hid[(size_t)tok * (Ec * FFc) + k0 + kb];
        uint32_t d = dst + (uint32_t)((mr * 20 + kb) << 2);
        cp16z(d, src, ok);
        cp16z(d + 32, src + 8, ok);
    }
    DEV void cpB(uint32_t dst, int n0, int k0, int tid, int z) const {
        cpB_dense(dst, w2 + (size_t)z * Ec * FFc * Dc, Dc, n0, k0, tid);
    }
    DEV void store2(int idx, int c, float v0, float v1, int z) const {
        int g = z;
        if (idx >= g_cnt[g]) return;
        int tok = g_perm[(g << 12) + idx];
        size_t o = (size_t)tok * Dc + c;
        float bs0 = b2[(size_t)(g * 2) * Dc + c] + b2[(size_t)(g * 2 + 1) * Dc + c];
        float bs1 = b2[(size_t)(g * 2) * Dc + c + 1] + b2[(size_t)(g * 2 + 1) * Dc + c + 1];
        out[o]     = 0.5f * v0 + 0.5f * bs0 + g_x2[o];
        out[o + 1] = 0.5f * v1 + 0.5f * bs1 + g_x2[o + 1];
    }
};

// ================= launch =================
constexpr size_t GEMM_SMEM = (size_t)GSTAGES * (ASZ + BSZ) * sizeof(float); // 56832
constexpr size_t FLASH_SMEM = (size_t)4 * FKSZ * sizeof(float);             // 69632

template <class P>
static void launch_gemm(dim3 grid, const P& p) {
    cudaFuncSetAttribute(gemm_mma<P>, cudaFuncAttributeMaxDynamicSharedMemorySize,
                         (int)GEMM_SMEM);
    gemm_mma<P><<<grid, 256, GEMM_SMEM>>>(p);
}

extern "C" void kernel_launch(void* const* d_in, const int* in_sizes, int n_in,
                              void* d_out, int out_size) {
    const float* x    = (const float*)d_in[0];
    const int*   gid  = (const int*)d_in[1];
    const float* ln1s = (const float*)d_in[2];
    const float* ln1b = (const float*)d_in[3];
    const float* ck   = (const float*)d_in[4];
    const float* cb   = (const float*)d_in[5];
    const float* ln2s = (const float*)d_in[6];
    const float* ln2b = (const float*)d_in[7];
    const float* wq   = (const float*)d_in[8];
    const float* bq   = (const float*)d_in[9];
    const float* wk   = (const float*)d_in[10];
    const float* bk   = (const float*)d_in[11];
    const float* wv   = (const float*)d_in[12];
    const float* bv   = (const float*)d_in[13];
    const float* wo   = (const float*)d_in[14];
    const float* bo   = (const float*)d_in[15];
    const float* w1   = (const float*)d_in[16];
    const float* b1   = (const float*)d_in[17];
    const float* w2   = (const float*)d_in[18];
    const float* b2   = (const float*)d_in[19];
    float* out = (float*)d_out;

    ln_kernel<0><<<Nc, 256>>>(x, ln1s, ln1b);
    {
        ConvProb p{ck, cb, x};
        launch_gemm(dim3(Dc / 128, Nc / 128, 1), p);
    }
    ln_kernel<1><<<Nc, 256>>>(x, ln2s, ln2b);
    {
        QKVProb p;
        p.w[0] = wq; p.w[1] = wk; p.w[2] = wv;
        p.b[0] = bq; p.b[1] = bk; p.b[2] = bv;
        launch_gemm(dim3(Dc / 128, Nc / 128, 3), p);
    }
    cudaFuncSetAttribute(flash_kernel, cudaFuncAttributeMaxDynamicSharedMemorySize,
                         (int)FLASH_SMEM);
    flash_kernel<<<dim3(Sc / 128, Bc * Hc), 256, FLASH_SMEM>>>();
    {
        OutProb p{wo, bo};
        launch_gemm(dim3(Dc / 128, Nc / 128, 1), p);
    }
    zero_cnt_kernel<<<1, 32>>>();
    scatter_kernel<<<Nc / 256, 256>>>(gid);
    {
        Moe1Prob p{w1, b1};
        launch_gemm(dim3(FFc / 128, Nc / 128, Gc * Ec), p);
    }
    {
        Moe2Prob p{w2, b2, out};
        launch_gemm(dim3(Dc / 128, Nc / 128, Gc), p);
    }
}

// round 5
// speedup vs baseline: 6.8427x; 1.9193x over previous
#include <cuda_runtime.h>
#include <cuda_fp16.h>
#include <math.h>
#include <stdint.h>
#include <stddef.h>

#define DEV __device__ __forceinline__

constexpr int Bc = 2, Sc = 2048, Dc = 512, Hc = 8, HDc = 64, KC = 31;
constexpr int FFc = 2048, Gc = 4, Ec = 2;
constexpr int Nc = Bc * Sc; // 4096 tokens

// ---------------- scratch ----------------
__device__ __align__(256) float g_x1[Nc * Dc];
__device__ __align__(256) float g_x2[Nc * Dc];
__device__ __align__(256) __half hh1[Nc * Dc];
__device__ __align__(256) __half hh2[Nc * Dc];
__device__ __align__(256) __half hq[Nc * Dc];
__device__ __align__(256) __half hk[Nc * Dc];
__device__ __align__(256) __half hv[Nc * Dc];
__device__ __align__(256) __half ho[Nc * Dc];
__device__ __align__(256) __half hx2[Nc * Dc];
__device__ __align__(256) __half hhid[(size_t)Nc * Ec * FFc];
// transposed half weights [n][k]
__device__ __align__(256) __half hckt[(size_t)Dc * KC * Dc];          // [512][15872]
__device__ __align__(256) __half hwqt[Dc * Dc];
__device__ __align__(256) __half hwkt[Dc * Dc];
__device__ __align__(256) __half hwvt[Dc * Dc];
__device__ __align__(256) __half hwot[Dc * Dc];
__device__ __align__(256) __half hw1t[(size_t)Gc * Ec * FFc * Dc];    // [g,e][2048][512]
__device__ __align__(256) __half hw2t[(size_t)Gc * Dc * Ec * FFc];    // [g][512][4096]
__device__ int g_perm[Gc * Nc];
__device__ int g_cnt[Gc];

DEV float gelu_f(float x) {
    const float c0 = 0.7978845608028654f;
    float t = c0 * (x + 0.044715f * x * x * x);
    return 0.5f * x * (1.0f + tanhf(t));
}

DEV void mma_f16(float (&c)[4], const uint32_t (&a)[4], const uint32_t (&b)[2]) {
    asm volatile(
        "mma.sync.aligned.m16n8k16.row.col.f32.f16.f16.f32 "
        "{%0,%1,%2,%3},{%4,%5,%6,%7},{%8,%9},{%0,%1,%2,%3};\n"
        : "+f"(c[0]), "+f"(c[1]), "+f"(c[2]), "+f"(c[3])
        : "r"(a[0]), "r"(a[1]), "r"(a[2]), "r"(a[3]), "r"(b[0]), "r"(b[1]));
}
DEV void ldm_x4(uint32_t (&r)[4], uint32_t addr) {
    asm volatile("ldmatrix.sync.aligned.m8n8.x4.shared.b16 {%0,%1,%2,%3}, [%4];"
                 : "=r"(r[0]), "=r"(r[1]), "=r"(r[2]), "=r"(r[3]) : "r"(addr));
}
DEV void ldm_x4t(uint32_t (&r)[4], uint32_t addr) {
    asm volatile("ldmatrix.sync.aligned.m8n8.x4.trans.shared.b16 {%0,%1,%2,%3}, [%4];"
                 : "=r"(r[0]), "=r"(r[1]), "=r"(r[2]), "=r"(r[3]) : "r"(addr));
}
DEV void cp16(uint32_t dst, const void* src) {
    asm volatile("cp.async.cg.shared.global [%0], [%1], 16;\n" :: "r"(dst), "l"(src));
}
DEV void cp16z(uint32_t dst, const void* src, bool pred) {
    int sz = pred ? 16 : 0;
    asm volatile("cp.async.cg.shared.global [%0], [%1], 16, %2;\n"
                 :: "r"(dst), "l"(src), "r"(sz));
}
DEV void cp_commit() { asm volatile("cp.async.commit_group;\n"); }
template <int N> DEV void cp_wait() { asm volatile("cp.async.wait_group %0;\n" :: "n"(N)); }
DEV uint32_t smem_u32(const void* p) { return (uint32_t)__cvta_generic_to_shared(p); }
DEV uint32_t packh2(float lo, float hi) {
    __half2 h = __floats2half2_rn(lo, hi);
    return *reinterpret_cast<uint32_t*>(&h);
}

// ---------------- weight transpose+convert: src [K][N] f32 -> dst [N][K] half ----------------
__global__ void tconv_kernel(const float* __restrict__ src, __half* __restrict__ dst,
                             int Kd, int Nd, int mode) {
    __shared__ float tile[32][33];
    int z = blockIdx.z;
    const float* s = src + (size_t)z * Kd * Nd;
    size_t doff;
    int dstride;
    if (mode == 0) { doff = (size_t)z * Kd * Nd; dstride = Kd; }
    else { doff = (size_t)(z >> 1) * (512 * 4096) + (size_t)(z & 1) * 2048; dstride = 4096; }
    int n0 = blockIdx.x * 32, k0 = blockIdx.y * 32;
    int tx = threadIdx.x, ty = threadIdx.y;
#pragma unroll
    for (int i = 0; i < 32; i += 8)
        tile[ty + i][tx] = s[(size_t)(k0 + ty + i) * Nd + n0 + tx];
    __syncthreads();
#pragma unroll
    for (int i = 0; i < 32; i += 8)
        dst[doff + (size_t)(n0 + ty + i) * dstride + k0 + tx] = __float2half(tile[tx][ty + i]);
}

// ---------------- LayerNorm (f32 in -> half out) ----------------
template <int WHICH>
__global__ void ln_kernel(const float* __restrict__ xin,
                          const float* __restrict__ sc,
                          const float* __restrict__ bi) {
    const float* src = (WHICH == 0) ? xin : g_x1;
    __half* dst = (WHICH == 0) ? hh1 : hh2;
    int row = blockIdx.x;
    const float* xr = src + (size_t)row * Dc;
    __half* orow = dst + (size_t)row * Dc;
    int t = threadIdx.x;
    float a = xr[t], b = xr[t + 256];
    float s = a + b, sq = a * a + b * b;
    __shared__ float sh[16];
#pragma unroll
    for (int o = 16; o; o >>= 1) {
        s += __shfl_xor_sync(0xffffffffu, s, o);
        sq += __shfl_xor_sync(0xffffffffu, sq, o);
    }
    int w = t >> 5;
    if ((t & 31) == 0) { sh[w] = s; sh[8 + w] = sq; }
    __syncthreads();
    if (t == 0) {
        float ts = 0.f, tq = 0.f;
#pragma unroll
        for (int i = 0; i < 8; i++) { ts += sh[i]; tq += sh[8 + i]; }
        float mean = ts * (1.0f / Dc);
        float var = tq * (1.0f / Dc) - mean * mean;
        sh[0] = mean;
        sh[1] = rsqrtf(var + 1e-6f);
    }
    __syncthreads();
    float mean = sh[0], rstd = sh[1];
    orow[t]       = __float2half((a - mean) * rstd * sc[t] + bi[t]);
    orow[t + 256] = __float2half((b - mean) * rstd * sc[t + 256] + bi[t + 256]);
}

// ---------------- routing ----------------
__global__ void zero_cnt_kernel() {
    if (threadIdx.x < Gc) g_cnt[threadIdx.x] = 0;
}
__global__ void scatter_kernel(const int* __restrict__ gid) {
    int n = blockIdx.x * 256 + threadIdx.x;
    if (n < Nc) {
        int g = gid[n];
        int p = atomicAdd(&g_cnt[g], 1);
        g_perm[(g << 12) + p] = n;
    }
}

// ---------------- fused flash attention (fp16 MMA) ----------------
constexpr int KVSTR = 72; // halves per row
__global__ __launch_bounds__(256) void flash_kernel() {
    __shared__ __align__(16) __half Ks[2][64 * KVSTR];
    __shared__ __align__(16) __half Vs[2][64 * KVSTR];
    const int tid = threadIdx.x, lane = tid & 31, warp = tid >> 5;
    const int g = lane >> 2, t4 = lane & 3;
    const int q0 = blockIdx.x * 128;
    const int z = blockIdx.y, b = z >> 3, h = z & 7;
    const int r0 = q0 + warp * 16 + g;

    // Q fragments: half2 pairs straight from gmem, scale 1/8 folded (exact)
    const __half2* Q2 = reinterpret_cast<const __half2*>(hq);
    size_t qb0 = ((size_t)(b << 11) + r0) * 256 + (h << 5);
    size_t qb1 = qb0 + 8 * 256;
    const __half2 scl = __float2half2_rn(0.125f);
    uint32_t qa[4][4];
#pragma unroll
    for (int ks = 0; ks < 4; ks++) {
        __half2 v0 = __hmul2(Q2[qb0 + ks * 8 + t4], scl);
        __half2 v1 = __hmul2(Q2[qb1 + ks * 8 + t4], scl);
        __half2 v2 = __hmul2(Q2[qb0 + ks * 8 + t4 + 4], scl);
        __half2 v3 = __hmul2(Q2[qb1 + ks * 8 + t4 + 4], scl);
        qa[ks][0] = *reinterpret_cast<uint32_t*>(&v0);
        qa[ks][1] = *reinterpret_cast<uint32_t*>(&v1);
        qa[ks][2] = *reinterpret_cast<uint32_t*>(&v2);
        qa[ks][3] = *reinterpret_cast<uint32_t*>(&v3);
    }

    float m0v = -1e30f, m1v = -1e30f, l0 = 0.f, l1 = 0.f;
    float oacc[8][4];
#pragma unroll
    for (int j = 0; j < 8; j++)
#pragma unroll
        for (int q = 0; q < 4; q++) oacc[j][q] = 0.f;

    // KV tile loader: 64 rows x 64 halves; thread -> row tid&63, segs (tid>>6), (tid>>6)+4
    const int lrow = tid & 63, lseg = tid >> 6;
    const __half* Kp = hk + (size_t)(b << 11) * Dc + (h << 6);
    const __half* Vp = hv + (size_t)(b << 11) * Dc + (h << 6);
    uint32_t kb0 = smem_u32(&Ks[0][0]), vb0 = smem_u32(&Vs[0][0]);

    auto issueKV = [&](int st, int slot) {
        const __half* kp = Kp + (size_t)(st * 64 + lrow) * Dc;
        const __half* vp = Vp + (size_t)(st * 64 + lrow) * Dc;
        uint32_t kd = kb0 + (uint32_t)((slot * 64 * KVSTR + lrow * KVSTR) * 2);
        uint32_t vd = vb0 + (uint32_t)((slot * 64 * KVSTR + lrow * KVSTR) * 2);
        cp16(kd + lseg * 16, kp + lseg * 8);
        cp16(kd + (lseg + 4) * 16, kp + (lseg + 4) * 8);
        cp16(vd + lseg * 16, vp + lseg * 8);
        cp16(vd + (lseg + 4) * 16, vp + (lseg + 4) * 8);
    };

    issueKV(0, 0);
    cp_commit();
    const float LOG2E = 1.4426950408889634f;

    for (int st = 0; st < 32; st++) {
        cp_wait<0>();
        __syncthreads();
        if (st + 1 < 32) issueKV(st + 1, (st + 1) & 1);
        cp_commit();

        uint32_t kaddr = kb0 + (uint32_t)((st & 1) * 64 * KVSTR * 2);
        uint32_t vaddr = vb0 + (uint32_t)((st & 1) * 64 * KVSTR * 2);

        // S = Q K^T
        float sc[8][4];
#pragma unroll
        for (int j = 0; j < 8; j++)
#pragma unroll
            for (int q = 0; q < 4; q++) sc[j][q] = 0.f;
#pragma unroll
        for (int ks = 0; ks < 4; ks++) {
            int kk = ks * 16;
#pragma unroll
            for (int nbp = 0; nbp < 4; nbp++) {
                uint32_t r[4];
                uint32_t addr = kaddr +
                    (uint32_t)(((nbp * 16 + ((lane >> 4) << 3) + (lane & 7)) * KVSTR +
                                kk + (lane & 8)) * 2);
                ldm_x4(r, addr);
                uint32_t b0[2] = {r[0], r[1]}, b1[2] = {r[2], r[3]};
                mma_f16(sc[nbp * 2], qa[ks], b0);
                mma_f16(sc[nbp * 2 + 1], qa[ks], b1);
            }
        }

        // online softmax
        float mx0 = m0v, mx1 = m1v;
#pragma unroll
        for (int j = 0; j < 8; j++) {
            mx0 = fmaxf(mx0, fmaxf(sc[j][0], sc[j][1]));
            mx1 = fmaxf(mx1, fmaxf(sc[j][2], sc[j][3]));
        }
        mx0 = fmaxf(mx0, __shfl_xor_sync(0xffffffffu, mx0, 1));
        mx0 = fmaxf(mx0, __shfl_xor_sync(0xffffffffu, mx0, 2));
        mx1 = fmaxf(mx1, __shfl_xor_sync(0xffffffffu, mx1, 1));
        mx1 = fmaxf(mx1, __shfl_xor_sync(0xffffffffu, mx1, 2));
        float al0 = exp2f((m0v - mx0) * LOG2E);
        float al1 = exp2f((m1v - mx1) * LOG2E);
        m0v = mx0; m1v = mx1;
        float s0 = 0.f, s1 = 0.f;
#pragma unroll
        for (int j = 0; j < 8; j++) {
            sc[j][0] = exp2f((sc[j][0] - mx0) * LOG2E);
            sc[j][1] = exp2f((sc[j][1] - mx0) * LOG2E);
            sc[j][2] = exp2f((sc[j][2] - mx1) * LOG2E);
            sc[j][3] = exp2f((sc[j][3] - mx1) * LOG2E);
            s0 += sc[j][0] + sc[j][1];
            s1 += sc[j][2] + sc[j][3];
        }
        s0 += __shfl_xor_sync(0xffffffffu, s0, 1);
        s0 += __shfl_xor_sync(0xffffffffu, s0, 2);
        s1 += __shfl_xor_sync(0xffffffffu, s1, 1);
        s1 += __shfl_xor_sync(0xffffffffu, s1, 2);
        l0 = l0 * al0 + s0;
        l1 = l1 * al1 + s1;
#pragma unroll
        for (int j = 0; j < 8; j++) {
            oacc[j][0] *= al0; oacc[j][1] *= al0;
            oacc[j][2] *= al1; oacc[j][3] *= al1;
        }

        // PV: P C-frags pack directly into fp16 A-frags (no shuffles)
#pragma unroll
        for (int ks = 0; ks < 4; ks++) {
            uint32_t pa[4];
            pa[0] = packh2(sc[2 * ks][0], sc[2 * ks][1]);
            pa[1] = packh2(sc[2 * ks][2], sc[2 * ks][3]);
            pa[2] = packh2(sc[2 * ks + 1][0], sc[2 * ks + 1][1]);
            pa[3] = packh2(sc[2 * ks + 1][2], sc[2 * ks + 1][3]);
#pragma unroll
            for (int hdp = 0; hdp < 4; hdp++) {
                uint32_t r[4];
                uint32_t addr = vaddr +
                    (uint32_t)(((ks * 16 + (lane & 15)) * KVSTR +
                                hdp * 16 + ((lane >> 4) << 3)) * 2);
                ldm_x4t(r, addr);
                uint32_t b0[2] = {r[0], r[1]}, b1[2] = {r[2], r[3]};
                mma_f16(oacc[hdp * 2], pa, b0);
                mma_f16(oacc[hdp * 2 + 1], pa, b1);
            }
        }
        __syncthreads();
    }

    float inv0 = 1.0f / l0, inv1 = 1.0f / l1;
    size_t ro0 = ((size_t)(b << 11) + r0) * Dc + (h << 6);
    size_t ro1 = ro0 + (size_t)8 * Dc;
#pragma unroll
    for (int jo = 0; jo < 8; jo++) {
        int c = jo * 8 + 2 * t4;
        ho[ro0 + c]     = __float2half(oacc[jo][0] * inv0);
        ho[ro0 + c + 1] = __float2half(oacc[jo][1] * inv0);
        ho[ro1 + c]     = __float2half(oacc[jo][2] * inv1);
        ho[ro1 + c + 1] = __float2half(oacc[jo][3] * inv1);
    }
}

// ---------------- half GEMM: 128x128 tile, BK=32, 3-stage cp.async, ldmatrix+m16n8k16 ----------------
constexpr int ASTR = 40;           // halves per smem row (32 + 8 pad)
constexpr int AST_H = 128 * ASTR;  // halves per stage (A or B)
constexpr int GSTAGES = 3;
constexpr size_t GEMM_SMEM = (size_t)GSTAGES * 2 * AST_H * sizeof(__half); // 61440

DEV void cpT_half(uint32_t dst, const __half* __restrict__ base, size_t ld,
                  int r0, int k0, int tid) {
    int rr = tid >> 1, kh = (tid & 1) << 4;
    const __half* src = base + (size_t)(r0 + rr) * ld + k0 + kh;
    uint32_t d = dst + (uint32_t)((rr * ASTR + kh) * 2);
    cp16(d, src);
    cp16(d + 16, src + 8);
}

template <class P>
__global__ __launch_bounds__(256, 2) void gemm_h(P p) {
    if (p.skip()) return;
    extern __shared__ __align__(16) char dynsm[];
    __half* As = reinterpret_cast<__half*>(dynsm);
    __half* Bs = As + GSTAGES * AST_H;
    uint32_t abase = smem_u32(As), bbase = smem_u32(Bs);

    int tid = threadIdx.x, lane = tid & 31, warp = tid >> 5;
    int m0 = blockIdx.y * 128, n0 = blockIdx.x * 128, z = blockIdx.z;
    int wm = warp >> 2, wn = warp & 3;
    int g = lane >> 2, t4 = lane & 3;

    float acc[4][4][4];
#pragma unroll
    for (int i = 0; i < 4; i++)
#pragma unroll
        for (int j = 0; j < 4; j++)
#pragma unroll
            for (int q = 0; q < 4; q++) acc[i][j][q] = 0.f;

    int T = p.K() >> 5;
#pragma unroll
    for (int s = 0; s < GSTAGES - 1; s++) {
        p.cpA(abase + (uint32_t)(s * AST_H * 2), m0, s * 32, tid, z);
        p.cpB(bbase + (uint32_t)(s * AST_H * 2), n0, s * 32, tid, z);
        cp_commit();
    }

    // ldmatrix address offsets (element units within a stage)
    int a_r = (lane & 15), a_c = ((lane >> 4) << 3);
    int b_r = ((lane >> 4) << 3) + (lane & 7), b_c = (lane & 8);

    for (int t = 0; t < T; t++) {
        cp_wait<GSTAGES - 2>();
        __syncthreads();
        int nf = t + GSTAGES - 1;
        if (nf < T) {
            int slo = nf % GSTAGES;
            p.cpA(abase + (uint32_t)(slo * AST_H * 2), m0, nf * 32, tid, z);
            p.cpB(bbase + (uint32_t)(slo * AST_H * 2), n0, nf * 32, tid, z);
        }
        cp_commit();

        uint32_t ab = abase + (uint32_t)((t % GSTAGES) * AST_H * 2);
        uint32_t bb = bbase + (uint32_t)((t % GSTAGES) * AST_H * 2);
#pragma unroll
        for (int ks = 0; ks < 2; ks++) {
            int kk = ks * 16;
            uint32_t af[4][4];
#pragma unroll
            for (int mi = 0; mi < 4; mi++) {
                uint32_t addr = ab +
                    (uint32_t)(((wm * 64 + mi * 16 + a_r) * ASTR + kk + a_c) * 2);
                ldm_x4(af[mi], addr);
            }
            uint32_t bf[4][2];
#pragma unroll
            for (int nb = 0; nb < 2; nb++) {
                uint32_t r[4];
                uint32_t addr = bb +
                    (uint32_t)(((wn * 32 + nb * 16 + b_r) * ASTR + kk + b_c) * 2);
                ldm_x4(r, addr);
                bf[nb * 2][0] = r[0]; bf[nb * 2][1] = r[1];
                bf[nb * 2 + 1][0] = r[2]; bf[nb * 2 + 1][1] = r[3];
            }
#pragma unroll
            for (int mi = 0; mi < 4; mi++)
#pragma unroll
                for (int nj = 0; nj < 4; nj++) mma_f16(acc[mi][nj], af[mi], bf[nj]);
        }
    }
#pragma unroll
    for (int mi = 0; mi < 4; mi++) {
        int r0 = m0 + wm * 64 + mi * 16 + g;
#pragma unroll
        for (int nj = 0; nj < 4; nj++) {
            int c = n0 + wn * 32 + nj * 8 + 2 * t4;
            p.store2(r0, c, acc[mi][nj][0], acc[mi][nj][1], z);
            p.store2(r0 + 8, c, acc[mi][nj][2], acc[mi][nj][3], z);
        }
    }
}

// ================= functors =================

struct ConvProb {
    const float* cb;
    const float* xres;
    DEV int K() const { return KC * Dc; }
    DEV bool skip() const { return false; }
    DEV void cpA(uint32_t dst, int m0, int k0, int tid, int) const {
        int mr = tid >> 1;
        int m = m0 + mr;
        int b = m >> 11, s = m & 2047;
        int kh = (tid & 1) << 4;
        int k = k0 + kh;
        int kk = k >> 9, ci = k & 511;   // 32-chunk never crosses a tap
        int sr = s + kk - 15;
        bool ok = (unsigned)sr < (unsigned)Sc;
        int srs = ok ? sr : 0;
        const __half* src = &hh1[(size_t)((b << 11) + srs) * Dc + ci];
        uint32_t d = dst + (uint32_t)((mr * ASTR + kh) * 2);
        cp16z(d, src, ok);
        cp16z(d + 16, src + 8, ok);
    }
    DEV void cpB(uint32_t dst, int n0, int k0, int tid, int) const {
        cpT_half(dst, hckt, (size_t)KC * Dc, n0, k0, tid);
    }
    DEV void store2(int m, int c, float v0, float v1, int) const {
        size_t o = (size_t)m * Dc + c;
        g_x1[o]     = gelu_f(v0 + cb[c])     + xres[o];
        g_x1[o + 1] = gelu_f(v1 + cb[c + 1]) + xres[o + 1];
    }
};

struct QKVProb {
    const float* b[3];
    DEV int K() const { return Dc; }
    DEV bool skip() const { return false; }
    DEV void cpA(uint32_t dst, int m0, int k0, int tid, int) const {
        cpT_half(dst, hh2, Dc, m0, k0, tid);
    }
    DEV void cpB(uint32_t dst, int n0, int k0, int tid, int z) const {
        const __half* w = (z == 0) ? hwqt : (z == 1) ? hwkt : hwvt;
        cpT_half(dst, w, Dc, n0, k0, tid);
    }
    DEV void store2(int m, int c, float v0, float v1, int z) const {
        __half* o = (z == 0) ? hq : (z == 1) ? hk : hv;
        const float* bias = b[z];
        size_t off = (size_t)m * Dc + c;
        o[off]     = __float2half(v0 + bias[c]);
        o[off + 1] = __float2half(v1 + bias[c + 1]);
    }
};

struct OutProb {
    const float* bo;
    DEV int K() const { return Dc; }
    DEV bool skip() const { return false; }
    DEV void cpA(uint32_t dst, int m0, int k0, int tid, int) const {
        cpT_half(dst, ho, Dc, m0, k0, tid);
    }
    DEV void cpB(uint32_t dst, int n0, int k0, int tid, int) const {
        cpT_half(dst, hwot, Dc, n0, k0, tid);
    }
    DEV void store2(int m, int c, float v0, float v1, int) const {
        size_t o = (size_t)m * Dc + c;
        float r0 = v0 + bo[c]     + g_x1[o];
        float r1 = v1 + bo[c + 1] + g_x1[o + 1];
        g_x2[o] = r0;     g_x2[o + 1] = r1;
        hx2[o] = __float2half(r0);
        hx2[o + 1] = __float2half(r1);
    }
};

struct Moe1Prob {
    const float* b1;
    DEV int K() const { return Dc; }
    DEV bool skip() const { return (int)(blockIdx.y * 128) >= g_cnt[blockIdx.z >> 1]; }
    DEV void cpA(uint32_t dst, int m0, int k0, int tid, int z) const {
        int g = z >> 1;
        int mr = tid >> 1;
        int i = m0 + mr;
        bool ok = i < g_cnt[g];
        int tok = ok ? g_perm[(g << 12) + i] : 0;
        int kh = (tid & 1) << 4;
        const __half* src = &hx2[(size_t)tok * Dc + k0 + kh];
        uint32_t d = dst + (uint32_t)((mr * ASTR + kh) * 2);
        cp16z(d, src, ok);
        cp16z(d + 16, src + 8, ok);
    }
    DEV void cpB(uint32_t dst, int n0, int k0, int tid, int z) const {
        cpT_half(dst, hw1t + (size_t)z * FFc * Dc, Dc, n0, k0, tid);
    }
    DEV void store2(int idx, int c, float v0, float v1, int z) const {
        int g = z >> 1, e = z & 1;
        if (idx >= g_cnt[g]) return;
        int tok = g_perm[(g << 12) + idx];
        size_t o = (size_t)tok * (Ec * FFc) + (e << 11) + c;
        const float* bb = &b1[(size_t)z * FFc + c];
        hhid[o]     = __float2half(gelu_f(v0 + bb[0]));
        hhid[o + 1] = __float2half(gelu_f(v1 + bb[1]));
    }
};

struct Moe2Prob {
    const float* b2;
    float* out;
    DEV int K() const { return Ec * FFc; }
    DEV bool skip() const { return (int)(blockIdx.y * 128) >= g_cnt[blockIdx.z]; }
    DEV void cpA(uint32_t dst, int m0, int k0, int tid, int z) const {
        int g = z;
        int mr = tid >> 1;
        int i = m0 + mr;
        bool ok = i < g_cnt[g];
        int tok = ok ? g_perm[(g << 12) + i] : 0;
        int kh = (tid & 1) << 4;
        const __half* src = &hhid[(size_t)tok * (Ec * FFc) + k0 + kh];
        uint32_t d = dst + (uint32_t)((mr * ASTR + kh) * 2);
        cp16z(d, src, ok);
        cp16z(d + 16, src + 8, ok);
    }
    DEV void cpB(uint32_t dst, int n0, int k0, int tid, int z) const {
        cpT_half(dst, hw2t + (size_t)z * Dc * Ec * FFc, (size_t)Ec * FFc, n0, k0, tid);
    }
    DEV void store2(int idx, int c, float v0, float v1, int z) const {
        int g = z;
        if (idx >= g_cnt[g]) return;
        int tok = g_perm[(g << 12) + idx];
        size_t o = (size_t)tok * Dc + c;
        float bs0 = b2[(size_t)(g * 2) * Dc + c] + b2[(size_t)(g * 2 + 1) * Dc + c];
        float bs1 = b2[(size_t)(g * 2) * Dc + c + 1] + b2[(size_t)(g * 2 + 1) * Dc + c + 1];
        out[o]     = 0.5f * v0 + 0.5f * bs0 + g_x2[o];
        out[o + 1] = 0.5f * v1 + 0.5f * bs1 + g_x2[o + 1];
    }
};

// ================= launch =================
template <class P>
static void launch_gemm(dim3 grid, const P& p) {
    cudaFuncSetAttribute(gemm_h<P>, cudaFuncAttributeMaxDynamicSharedMemorySize,
                         (int)GEMM_SMEM);
    gemm_h<P><<<grid, 256, GEMM_SMEM>>>(p);
}

extern "C" void kernel_launch(void* const* d_in, const int* in_sizes, int n_in,
                              void* d_out, int out_size) {
    const float* x    = (const float*)d_in[0];
    const int*   gid  = (const int*)d_in[1];
    const float* ln1s = (const float*)d_in[2];
    const float* ln1b = (const float*)d_in[3];
    const float* ck   = (const float*)d_in[4];
    const float* cb   = (const float*)d_in[5];
    const float* ln2s = (const float*)d_in[6];
    const float* ln2b = (const float*)d_in[7];
    const float* wq   = (const float*)d_in[8];
    const float* bq   = (const float*)d_in[9];
    const float* wk   = (const float*)d_in[10];
    const float* bk   = (const float*)d_in[11];
    const float* wv   = (const float*)d_in[12];
    const float* bv   = (const float*)d_in[13];
    const float* wo   = (const float*)d_in[14];
    const float* bo   = (const float*)d_in[15];
    const float* w1   = (const float*)d_in[16];
    const float* b1   = (const float*)d_in[17];
    const float* w2   = (const float*)d_in[18];
    const float* b2   = (const float*)d_in[19];
    float* out = (float*)d_out;

    __half* d_hckt; cudaGetSymbolAddress((void**)&d_hckt, hckt);
    __half* d_hwqt; cudaGetSymbolAddress((void**)&d_hwqt, hwqt);
    __half* d_hwkt; cudaGetSymbolAddress((void**)&d_hwkt, hwkt);
    __half* d_hwvt; cudaGetSymbolAddress((void**)&d_hwvt, hwvt);
    __half* d_hwot; cudaGetSymbolAddress((void**)&d_hwot, hwot);
    __half* d_hw1t; cudaGetSymbolAddress((void**)&d_hw1t, hw1t);
    __half* d_hw2t; cudaGetSymbolAddress((void**)&d_hw2t, hw2t);

    dim3 tb(32, 8);
    tconv_kernel<<<dim3(Dc / 32, KC * Dc / 32, 1), tb>>>(ck, d_hckt, KC * Dc, Dc, 0);
    tconv_kernel<<<dim3(Dc / 32, Dc / 32, 1), tb>>>(wq, d_hwqt, Dc, Dc, 0);
    tconv_kernel<<<dim3(Dc / 32, Dc / 32, 1), tb>>>(wk, d_hwkt, Dc, Dc, 0);
    tconv_kernel<<<dim3(Dc / 32, Dc / 32, 1), tb>>>(wv, d_hwvt, Dc, Dc, 0);
    tconv_kernel<<<dim3(Dc / 32, Dc / 32, 1), tb>>>(wo, d_hwot, Dc, Dc, 0);
    tconv_kernel<<<dim3(FFc / 32, Dc / 32, Gc * Ec), tb>>>(w1, d_hw1t, Dc, FFc, 0);
    tconv_kernel<<<dim3(Dc / 32, FFc / 32, Gc * Ec), tb>>>(w2, d_hw2t, FFc, Dc, 1);

    ln_kernel<0><<<Nc, 256>>>(x, ln1s, ln1b);
    {
        ConvProb p{cb, x};
        launch_gemm(dim3(Dc / 128, Nc / 128, 1), p);
    }
    ln_kernel<1><<<Nc, 256>>>(x, ln2s, ln2b);
    {
        QKVProb p;
        p.b[0] = bq; p.b[1] = bk; p.b[2] = bv;
        launch_gemm(dim3(Dc / 128, Nc / 128, 3), p);
    }
    flash_kernel<<<dim3(Sc / 128, Bc * Hc), 256>>>();
    {
        OutProb p{bo};
        launch_gemm(dim3(Dc / 128, Nc / 128, 1), p);
    }
    zero_cnt_kernel<<<1, 32>>>();
    scatter_kernel<<<Nc / 256, 256>>>(gid);
    {
        Moe1Prob p{b1};
        launch_gemm(dim3(FFc / 128, Nc / 128, Gc * Ec), p);
    }
    {
        Moe2Prob p{b2, out};
        launch_gemm(dim3(Dc / 128, Nc / 128, Gc), p);
    }
}

// round 7
// speedup vs baseline: 8.0482x; 1.1762x over previous
#include <cuda_runtime.h>
#include <cuda_fp16.h>
#include <math.h>
#include <stdint.h>
#include <stddef.h>

#define DEV __device__ __forceinline__

constexpr int Bc = 2, Sc = 2048, Dc = 512, Hc = 8, HDc = 64, KC = 31;
constexpr int FFc = 2048, Gc = 4, Ec = 2;
constexpr int Nc = Bc * Sc; // 4096 tokens

// ---------------- scratch ----------------
__device__ __align__(256) float g_x1[Nc * Dc];
__device__ __align__(256) float g_x2[Nc * Dc];
__device__ __align__(256) __half hh1[Nc * Dc];
__device__ __align__(256) __half hh2[Nc * Dc];
__device__ __align__(256) __half hq[Nc * Dc];
__device__ __align__(256) __half hk[Nc * Dc];
__device__ __align__(256) __half hv[Nc * Dc];
__device__ __align__(256) __half ho[Nc * Dc];
__device__ __align__(256) __half hx2[Nc * Dc];
__device__ __align__(256) __half hhid[(size_t)Nc * Ec * FFc];
// half weights, native [k][n] layouts
__device__ __align__(256) __half hck[(size_t)KC * Dc * Dc];          // [15872][512]
__device__ __align__(256) __half hwq[Dc * Dc];
__device__ __align__(256) __half hwk[Dc * Dc];
__device__ __align__(256) __half hwv[Dc * Dc];
__device__ __align__(256) __half hwo[Dc * Dc];
__device__ __align__(256) __half hw1[(size_t)Gc * Ec * Dc * FFc];    // [g,e][512][2048]
__device__ __align__(256) __half hw2[(size_t)Gc * Ec * FFc * Dc];    // [g][4096][512]
__device__ int g_perm[Gc * Nc];
__device__ int g_cnt[Gc];

DEV float gelu_f(float x) {
    const float c0 = 0.7978845608028654f;
    float t = c0 * (x + 0.044715f * x * x * x);
    return 0.5f * x * (1.0f + tanhf(t));
}

// ---------------- low-level helpers ----------------
DEV void cp16(uint32_t dst, const void* src) {
    asm volatile("cp.async.cg.shared.global [%0], [%1], 16;\n" :: "r"(dst), "l"(src));
}
DEV void cp16z(uint32_t dst, const void* src, bool pred) {
    int sz = pred ? 16 : 0;
    asm volatile("cp.async.cg.shared.global [%0], [%1], 16, %2;\n"
                 :: "r"(dst), "l"(src), "r"(sz));
}
DEV void cp_commit() { asm volatile("cp.async.commit_group;\n"); }
template <int N> DEV void cp_wait() { asm volatile("cp.async.wait_group %0;\n" :: "n"(N)); }
DEV uint32_t smem_u32(const void* p) { return (uint32_t)__cvta_generic_to_shared(p); }
DEV uint32_t packh2(float lo, float hi) {
    __half2 h = __floats2half2_rn(lo, hi);
    return *reinterpret_cast<uint32_t*>(&h);
}
DEV void mma_f16(float (&c)[4], const uint32_t (&a)[4], const uint32_t (&b)[2]) {
    asm volatile(
        "mma.sync.aligned.m16n8k16.row.col.f32.f16.f16.f32 "
        "{%0,%1,%2,%3},{%4,%5,%6,%7},{%8,%9},{%0,%1,%2,%3};\n"
        : "+f"(c[0]), "+f"(c[1]), "+f"(c[2]), "+f"(c[3])
        : "r"(a[0]), "r"(a[1]), "r"(a[2]), "r"(a[3]), "r"(b[0]), "r"(b[1]));
}
DEV void ldm_x4(uint32_t (&r)[4], uint32_t addr) {
    asm volatile("ldmatrix.sync.aligned.m8n8.x4.shared.b16 {%0,%1,%2,%3}, [%4];"
                 : "=r"(r[0]), "=r"(r[1]), "=r"(r[2]), "=r"(r[3]) : "r"(addr));
}
DEV void ldm_x4t(uint32_t (&r)[4], uint32_t addr) {
    asm volatile("ldmatrix.sync.aligned.m8n8.x4.trans.shared.b16 {%0,%1,%2,%3}, [%4];"
                 : "=r"(r[0]), "=r"(r[1]), "=r"(r[2]), "=r"(r[3]) : "r"(addr));
}

// ---------------- f32 -> f16 streaming convert ----------------
__global__ void cvt_kernel(const float* __restrict__ src, __half* __restrict__ dst,
                           int n4) { // n4 = elements/4
    int i = blockIdx.x * blockDim.x + threadIdx.x;
    int stride = gridDim.x * blockDim.x;
    for (; i < n4; i += stride) {
        float4 v = reinterpret_cast<const float4*>(src)[i];
        __half2 lo = __floats2half2_rn(v.x, v.y);
        __half2 hi = __floats2half2_rn(v.z, v.w);
        uint2 o;
        o.x = *reinterpret_cast<uint32_t*>(&lo);
        o.y = *reinterpret_cast<uint32_t*>(&hi);
        reinterpret_cast<uint2*>(dst)[i] = o;
    }
}

// ---------------- LayerNorm ----------------
template <int WHICH>
__global__ void ln_kernel(const float* __restrict__ xin,
                          const float* __restrict__ sc,
                          const float* __restrict__ bi) {
    const float* src = (WHICH == 0) ? xin : g_x1;
    __half* dst = (WHICH == 0) ? hh1 : hh2;
    int row = blockIdx.x;
    const float* xr = src + (size_t)row * Dc;
    __half* orow = dst + (size_t)row * Dc;
    int t = threadIdx.x;
    float a = xr[t], b = xr[t + 256];
    float s = a + b, sq = a * a + b * b;
    __shared__ float sh[16];
#pragma unroll
    for (int o = 16; o; o >>= 1) {
        s += __shfl_xor_sync(0xffffffffu, s, o);
        sq += __shfl_xor_sync(0xffffffffu, sq, o);
    }
    int w = t >> 5;
    if ((t & 31) == 0) { sh[w] = s; sh[8 + w] = sq; }
    __syncthreads();
    if (t == 0) {
        float ts = 0.f, tq = 0.f;
#pragma unroll
        for (int i = 0; i < 8; i++) { ts += sh[i]; tq += sh[8 + i]; }
        float mean = ts * (1.0f / Dc);
        float var = tq * (1.0f / Dc) - mean * mean;
        sh[0] = mean;
        sh[1] = rsqrtf(var + 1e-6f);
    }
    __syncthreads();
    float mean = sh[0], rstd = sh[1];
    orow[t]       = __float2half((a - mean) * rstd * sc[t] + bi[t]);
    orow[t + 256] = __float2half((b - mean) * rstd * sc[t + 256] + bi[t + 256]);
}

// ---------------- routing ----------------
__global__ void zero_cnt_kernel() {
    if (threadIdx.x < Gc) g_cnt[threadIdx.x] = 0;
}
__global__ void scatter_kernel(const int* __restrict__ gid) {
    int n = blockIdx.x * 256 + threadIdx.x;
    if (n < Nc) {
        int g = gid[n];
        int p = atomicAdd(&g_cnt[g], 1);
        g_perm[(g << 12) + p] = n;
    }
}

// ---------------- fused flash attention (fp16 mma.sync) ----------------
constexpr int KVSTR = 72;
__global__ __launch_bounds__(256) void flash_kernel() {
    __shared__ __align__(16) __half Ks[2][64 * KVSTR];
    __shared__ __align__(16) __half Vs[2][64 * KVSTR];
    const int tid = threadIdx.x, lane = tid & 31, warp = tid >> 5;
    const int g = lane >> 2, t4 = lane & 3;
    const int q0 = blockIdx.x * 128;
    const int z = blockIdx.y, b = z >> 3, h = z & 7;
    const int r0 = q0 + warp * 16 + g;

    const __half2* Q2 = reinterpret_cast<const __half2*>(hq);
    size_t qb0 = ((size_t)(b << 11) + r0) * 256 + (h << 5);
    size_t qb1 = qb0 + 8 * 256;
    const __half2 scl = __float2half2_rn(0.125f);
    uint32_t qa[4][4];
#pragma unroll
    for (int ks = 0; ks < 4; ks++) {
        __half2 v0 = __hmul2(Q2[qb0 + ks * 8 + t4], scl);
        __half2 v1 = __hmul2(Q2[qb1 + ks * 8 + t4], scl);
        __half2 v2 = __hmul2(Q2[qb0 + ks * 8 + t4 + 4], scl);
        __half2 v3 = __hmul2(Q2[qb1 + ks * 8 + t4 + 4], scl);
        qa[ks][0] = *reinterpret_cast<uint32_t*>(&v0);
        qa[ks][1] = *reinterpret_cast<uint32_t*>(&v1);
        qa[ks][2] = *reinterpret_cast<uint32_t*>(&v2);
        qa[ks][3] = *reinterpret_cast<uint32_t*>(&v3);
    }

    float m0v = -1e30f, m1v = -1e30f, l0 = 0.f, l1 = 0.f;
    float oacc[8][4];
#pragma unroll
    for (int j = 0; j < 8; j++)
#pragma unroll
        for (int q = 0; q < 4; q++) oacc[j][q] = 0.f;

    const int lrow = tid & 63, lseg = tid >> 6;
    const __half* Kp = hk + (size_t)(b << 11) * Dc + (h << 6);
    const __half* Vp = hv + (size_t)(b << 11) * Dc + (h << 6);
    uint32_t kb0 = smem_u32(&Ks[0][0]), vb0 = smem_u32(&Vs[0][0]);

    auto issueKV = [&](int st, int slot) {
        const __half* kp = Kp + (size_t)(st * 64 + lrow) * Dc;
        const __half* vp = Vp + (size_t)(st * 64 + lrow) * Dc;
        uint32_t kd = kb0 + (uint32_t)((slot * 64 * KVSTR + lrow * KVSTR) * 2);
        uint32_t vd = vb0 + (uint32_t)((slot * 64 * KVSTR + lrow * KVSTR) * 2);
        cp16(kd + lseg * 16, kp + lseg * 8);
        cp16(kd + (lseg + 4) * 16, kp + (lseg + 4) * 8);
        cp16(vd + lseg * 16, vp + lseg * 8);
        cp16(vd + (lseg + 4) * 16, vp + (lseg + 4) * 8);
    };

    issueKV(0, 0);
    cp_commit();
    const float LOG2E = 1.4426950408889634f;

    for (int st = 0; st < 32; st++) {
        cp_wait<0>();
        __syncthreads();
        if (st + 1 < 32) issueKV(st + 1, (st + 1) & 1);
        cp_commit();

        uint32_t kaddr = kb0 + (uint32_t)((st & 1) * 64 * KVSTR * 2);
        uint32_t vaddr = vb0 + (uint32_t)((st & 1) * 64 * KVSTR * 2);

        float sc[8][4];
#pragma unroll
        for (int j = 0; j < 8; j++)
#pragma unroll
            for (int q = 0; q < 4; q++) sc[j][q] = 0.f;
#pragma unroll
        for (int ks = 0; ks < 4; ks++) {
            int kk = ks * 16;
#pragma unroll
            for (int nbp = 0; nbp < 4; nbp++) {
                uint32_t r[4];
                uint32_t addr = kaddr +
                    (uint32_t)(((nbp * 16 + ((lane >> 4) << 3) + (lane & 7)) * KVSTR +
                                kk + (lane & 8)) * 2);
                ldm_x4(r, addr);
                uint32_t b0[2] = {r[0], r[1]}, b1[2] = {r[2], r[3]};
                mma_f16(sc[nbp * 2], qa[ks], b0);
                mma_f16(sc[nbp * 2 + 1], qa[ks], b1);
            }
        }

        float mx0 = m0v, mx1 = m1v;
#pragma unroll
        for (int j = 0; j < 8; j++) {
            mx0 = fmaxf(mx0, fmaxf(sc[j][0], sc[j][1]));
            mx1 = fmaxf(mx1, fmaxf(sc[j][2], sc[j][3]));
        }
        mx0 = fmaxf(mx0, __shfl_xor_sync(0xffffffffu, mx0, 1));
        mx0 = fmaxf(mx0, __shfl_xor_sync(0xffffffffu, mx0, 2));
        mx1 = fmaxf(mx1, __shfl_xor_sync(0xffffffffu, mx1, 1));
        mx1 = fmaxf(mx1, __shfl_xor_sync(0xffffffffu, mx1, 2));
        float al0 = exp2f((m0v - mx0) * LOG2E);
        float al1 = exp2f((m1v - mx1) * LOG2E);
        m0v = mx0; m1v = mx1;
        float s0 = 0.f, s1 = 0.f;
#pragma unroll
        for (int j = 0; j < 8; j++) {
            sc[j][0] = exp2f((sc[j][0] - mx0) * LOG2E);
            sc[j][1] = exp2f((sc[j][1] - mx0) * LOG2E);
            sc[j][2] = exp2f((sc[j][2] - mx1) * LOG2E);
            sc[j][3] = exp2f((sc[j][3] - mx1) * LOG2E);
            s0 += sc[j][0] + sc[j][1];
            s1 += sc[j][2] + sc[j][3];
        }
        s0 += __shfl_xor_sync(0xffffffffu, s0, 1);
        s0 += __shfl_xor_sync(0xffffffffu, s0, 2);
        s1 += __shfl_xor_sync(0xffffffffu, s1, 1);
        s1 += __shfl_xor_sync(0xffffffffu, s1, 2);
        l0 = l0 * al0 + s0;
        l1 = l1 * al1 + s1;
#pragma unroll
        for (int j = 0; j < 8; j++) {
            oacc[j][0] *= al0; oacc[j][1] *= al0;
            oacc[j][2] *= al1; oacc[j][3] *= al1;
        }

#pragma unroll
        for (int ks = 0; ks < 4; ks++) {
            uint32_t pa[4];
            pa[0] = packh2(sc[2 * ks][0], sc[2 * ks][1]);
            pa[1] = packh2(sc[2 * ks][2], sc[2 * ks][3]);
            pa[2] = packh2(sc[2 * ks + 1][0], sc[2 * ks + 1][1]);
            pa[3] = packh2(sc[2 * ks + 1][2], sc[2 * ks + 1][3]);
#pragma unroll
            for (int hdp = 0; hdp < 4; hdp++) {
                uint32_t r[4];
                uint32_t addr = vaddr +
                    (uint32_t)(((ks * 16 + (lane & 15)) * KVSTR +
                                hdp * 16 + ((lane >> 4) << 3)) * 2);
                ldm_x4t(r, addr);
                uint32_t b0[2] = {r[0], r[1]}, b1[2] = {r[2], r[3]};
                mma_f16(oacc[hdp * 2], pa, b0);
                mma_f16(oacc[hdp * 2 + 1], pa, b1);
            }
        }
        __syncthreads();
    }

    float inv0 = 1.0f / l0, inv1 = 1.0f / l1;
    size_t ro0 = ((size_t)(b << 11) + r0) * Dc + (h << 6);
    size_t ro1 = ro0 + (size_t)8 * Dc;
#pragma unroll
    for (int jo = 0; jo < 8; jo++) {
        int c = jo * 8 + 2 * t4;
        ho[ro0 + c]     = __float2half(oacc[jo][0] * inv0);
        ho[ro0 + c + 1] = __float2half(oacc[jo][1] * inv0);
        ho[ro1 + c]     = __float2half(oacc[jo][2] * inv1);
        ho[ro1 + c + 1] = __float2half(oacc[jo][3] * inv1);
    }
}

// ---------------- fp16 GEMM: 64x128 tile, BK=32, 4-stage cp.async ----------------
// A stage: [64][ASTR=40] halves (m-major); B stage: [32][BSTR=136] halves (k-major, trans ldmatrix)
constexpr int ASTR = 40;
constexpr int BSTR = 136;
constexpr int A_ST = 64 * ASTR;          // halves
constexpr int B_ST = 32 * BSTR;          // halves
constexpr int STG_H = A_ST + B_ST;       // halves per stage
constexpr int GS = 4;
constexpr size_t GEMM_SMEM = (size_t)GS * STG_H * sizeof(__half); // 55296 B

DEV uint32_t stA(uint32_t sm0, int s) { return sm0 + (uint32_t)(s * STG_H * 2); }
DEV uint32_t stB(uint32_t sm0, int s) { return sm0 + (uint32_t)((s * STG_H + A_ST) * 2); }

// A fill: 64 rows x 32 halves; thread -> row tid>>2, 8 halves at (tid&3)*8
DEV void cpA_rows(uint32_t base, const __half* src_row, int tid, bool pred) {
    int row = tid >> 2, kh = (tid & 3) << 3;
    cp16z(base + (uint32_t)((row * ASTR + kh) * 2), src_row + kh, pred);
}
DEV void cpA_dense(uint32_t base, const __half* __restrict__ W, size_t ld,
                   int m0, int k0, int tid) {
    int row = tid >> 2, kh = (tid & 3) << 3;
    cp16(base + (uint32_t)((row * ASTR + kh) * 2),
         W + (size_t)(m0 + row) * ld + k0 + kh);
}
// B fill: 32 k-rows x 128 n-halves; thread -> row tid>>3, 16 halves at (tid&7)*16
DEV void cpB_dense(uint32_t base, const __half* __restrict__ W, size_t ldn,
                   int n0, int k0, int tid) {
    int row = tid >> 3, nh = (tid & 7) << 4;
    const __half* src = W + (size_t)(k0 + row) * ldn + n0 + nh;
    uint32_t d = base + (uint32_t)((row * BSTR + nh) * 2);
    cp16(d, src);
    cp16(d + 16, src + 8);
}

template <class P>
__global__ __launch_bounds__(256, 2) void gemm_h(P p) {
    if (p.skip()) return;
    extern __shared__ __align__(16) char dynsm[];
    uint32_t sm0 = smem_u32(dynsm);

    int tid = threadIdx.x, lane = tid & 31, warp = tid >> 5;
    int m0 = blockIdx.y * 64, n0 = blockIdx.x * 128, z = blockIdx.z;
    int wm = warp >> 2, wn = warp & 3;   // 2 x 4 warps, warptile 32x32
    int g = lane >> 2, t4 = lane & 3;

    float acc[2][4][4];
#pragma unroll
    for (int i = 0; i < 2; i++)
#pragma unroll
        for (int j = 0; j < 4; j++)
#pragma unroll
            for (int q = 0; q < 4; q++) acc[i][j][q] = 0.f;

    int T = p.K() >> 5;
#pragma unroll
    for (int s = 0; s < GS - 1; s++) {
        p.cpA(stA(sm0, s), m0, s * 32, tid, z);
        p.cpB(stB(sm0, s), n0, s * 32, tid, z);
        cp_commit();
    }

    int a_r = lane & 15, a_c = (lane >> 4) << 3;
    int b_kr = lane & 15, b_nc = (lane >> 4) << 3;

    for (int t = 0; t < T; t++) {
        cp_wait<GS - 2>();
        __syncthreads();
        int nf = t + GS - 1;
        if (nf < T) {
            int s = nf & (GS - 1);
            p.cpA(stA(sm0, s), m0, nf * 32, tid, z);
            p.cpB(stB(sm0, s), n0, nf * 32, tid, z);
        }
        cp_commit();

        uint32_t ab = stA(sm0, t & (GS - 1));
        uint32_t bb = stB(sm0, t & (GS - 1));
#pragma unroll
        for (int ks = 0; ks < 2; ks++) {
            int kk = ks * 16;
            uint32_t af[2][4];
#pragma unroll
            for (int mi = 0; mi < 2; mi++) {
                uint32_t addr = ab +
                    (uint32_t)(((wm * 32 + mi * 16 + a_r) * ASTR + kk + a_c) * 2);
                ldm_x4(af[mi], addr);
            }
            uint32_t bf[4][2];
#pragma unroll
            for (int nb = 0; nb < 2; nb++) {
                uint32_t r[4];
                uint32_t addr = bb +
                    (uint32_t)(((kk + b_kr) * BSTR + wn * 32 + nb * 16 + b_nc) * 2);
                ldm_x4t(r, addr);
                bf[nb * 2][0] = r[0]; bf[nb * 2][1] = r[1];
                bf[nb * 2 + 1][0] = r[2]; bf[nb * 2 + 1][1] = r[3];
            }
#pragma unroll
            for (int mi = 0; mi < 2; mi++)
#pragma unroll
                for (int nj = 0; nj < 4; nj++) mma_f16(acc[mi][nj], af[mi], bf[nj]);
        }
    }
#pragma unroll
    for (int mi = 0; mi < 2; mi++) {
        int r0 = m0 + wm * 32 + mi * 16 + g;
#pragma unroll
        for (int nj = 0; nj < 4; nj++) {
            int c = n0 + wn * 32 + nj * 8 + 2 * t4;
            p.store2(r0, c, acc[mi][nj][0], acc[mi][nj][1], z);
            p.store2(r0 + 8, c, acc[mi][nj][2], acc[mi][nj][3], z);
        }
    }
}

// ================= functors =================

struct ConvProb {
    const float* cb;
    const float* xres;
    DEV int K() const { return KC * Dc; }
    DEV bool skip() const { return false; }
    DEV void cpA(uint32_t base, int m0, int k0, int tid, int) const {
        int row = tid >> 2;
        int m = m0 + row;
        int b = m >> 11, s = m & 2047;
        int k = k0 + ((tid & 3) << 3);
        int kk = k >> 9, ci = k & 511;   // 8-half chunk never crosses a tap
        int sr = s + kk - 15;
        bool ok = (unsigned)sr < (unsigned)Sc;
        const __half* src = &hh1[(size_t)((b << 11) + (ok ? sr : 0)) * Dc + ci];
        cp16z(base + (uint32_t)((row * ASTR + ((tid & 3) << 3)) * 2), src, ok);
    }
    DEV void cpB(uint32_t base, int n0, int k0, int tid, int) const {
        cpB_dense(base, hck, Dc, n0, k0, tid);
    }
    DEV void store2(int m, int c, float v0, float v1, int) const {
        size_t o = (size_t)m * Dc + c;
        g_x1[o]     = gelu_f(v0 + cb[c])     + xres[o];
        g_x1[o + 1] = gelu_f(v1 + cb[c + 1]) + xres[o + 1];
    }
};

struct QKVProb {
    const float* b[3];
    DEV int K() const { return Dc; }
    DEV bool skip() const { return false; }
    DEV void cpA(uint32_t base, int m0, int k0, int tid, int) const {
        cpA_dense(base, hh2, Dc, m0, k0, tid);
    }
    DEV void cpB(uint32_t base, int n0, int k0, int tid, int z) const {
        const __half* w = (z == 0) ? hwq : (z == 1) ? hwk : hwv;
        cpB_dense(base, w, Dc, n0, k0, tid);
    }
    DEV void store2(int m, int c, float v0, float v1, int z) const {
        __half* o = (z == 0) ? hq : (z == 1) ? hk : hv;
        const float* bias = b[z];
        size_t off = (size_t)m * Dc + c;
        o[off]     = __float2half(v0 + bias[c]);
        o[off + 1] = __float2half(v1 + bias[c + 1]);
    }
};

struct OutProb {
    const float* bo;
    DEV int K() const { return Dc; }
    DEV bool skip() const { return false; }
    DEV void cpA(uint32_t base, int m0, int k0, int tid, int) const {
        cpA_dense(base, ho, Dc, m0, k0, tid);
    }
    DEV void cpB(uint32_t base, int n0, int k0, int tid, int) const {
        cpB_dense(base, hwo, Dc, n0, k0, tid);
    }
    DEV void store2(int m, int c, float v0, float v1, int) const {
        size_t o = (size_t)m * Dc + c;
        float r0 = v0 + bo[c]     + g_x1[o];
        float r1 = v1 + bo[c + 1] + g_x1[o + 1];
        g_x2[o] = r0;     g_x2[o + 1] = r1;
        hx2[o] = __float2half(r0);
        hx2[o + 1] = __float2half(r1);
    }
};

struct Moe1Prob {
    const float* b1;
    DEV int K() const { return Dc; }
    DEV bool skip() const { return (int)(blockIdx.y * 64) >= g_cnt[blockIdx.z >> 1]; }
    DEV void cpA(uint32_t base, int m0, int k0, int tid, int z) const {
        int g = z >> 1;
        int row = tid >> 2;
        int i = m0 + row;
        bool ok = i < g_cnt[g];
        int tok = ok ? g_perm[(g << 12) + i] : 0;
        int kh = (tid & 3) << 3;
        cp16z(base + (uint32_t)((row * ASTR + kh) * 2),
              &hx2[(size_t)tok * Dc + k0 + kh], ok);
    }
    DEV void cpB(uint32_t base, int n0, int k0, int tid, int z) const {
        cpB_dense(base, hw1 + (size_t)z * Dc * FFc, FFc, n0, k0, tid);
    }
    DEV void store2(int idx, int c, float v0, float v1, int z) const {
        int g = z >> 1, e = z & 1;
        if (idx >= g_cnt[g]) return;
        int tok = g_perm[(g << 12) + idx];
        size_t o = (size_t)tok * (Ec * FFc) + (e << 11) + c;
        const float* bb = &b1[(size_t)z * FFc + c];
        hhid[o]     = __float2half(gelu_f(v0 + bb[0]));
        hhid[o + 1] = __float2half(gelu_f(v1 + bb[1]));
    }
};

struct Moe2Prob {
    const float* b2;
    float* out;
    DEV int K() const { return Ec * FFc; }
    DEV bool skip() const { return (int)(blockIdx.y * 64) >= g_cnt[blockIdx.z]; }
    DEV void cpA(uint32_t base, int m0, int k0, int tid, int z) const {
        int g = z;
        int row = tid >> 2;
        int i = m0 + row;
        bool ok = i < g_cnt[g];
        int tok = ok ? g_perm[(g << 12) + i] : 0;
        int kh = (tid & 3) << 3;
        cp16z(base + (uint32_t)((row * ASTR + kh) * 2),
              &hhid[(size_t)tok * (Ec * FFc) + k0 + kh], ok);
    }
    DEV void cpB(uint32_t base, int n0, int k0, int tid, int z) const {
        cpB_dense(base, hw2 + (size_t)z * Ec * FFc * Dc, Dc, n0, k0, tid);
    }
    DEV void store2(int idx, int c, float v0, float v1, int z) const {
        int g = z;
        if (idx >= g_cnt[g]) return;
        int tok = g_perm[(g << 12) + idx];
        size_t o = (size_t)tok * Dc + c;
        float bs0 = b2[(size_t)(g * 2) * Dc + c] + b2[(size_t)(g * 2 + 1) * Dc + c];
        float bs1 = b2[(size_t)(g * 2) * Dc + c + 1] + b2[(size_t)(g * 2 + 1) * Dc + c + 1];
        out[o]     = 0.5f * v0 + 0.5f * bs0 + g_x2[o];
        out[o + 1] = 0.5f * v1 + 0.5f * bs1 + g_x2[o + 1];
    }
};

// ================= launch =================
template <class P>
static void launch_gemm(dim3 grid, const P& p) {
    cudaFuncSetAttribute(gemm_h<P>, cudaFuncAttributeMaxDynamicSharedMemorySize,
                         (int)GEMM_SMEM);
    gemm_h<P><<<grid, 256, GEMM_SMEM>>>(p);
}

static void cvt(const float* s, __half* d, size_t n) {
    int n4 = (int)(n >> 2);
    int grid = (n4 + 255) / 256;
    if (grid > 1184) grid = 1184;
    cvt_kernel<<<grid, 256>>>(s, d, n4);
}

extern "C" void kernel_launch(void* const* d_in, const int* in_sizes, int n_in,
                              void* d_out, int out_size) {
    const float* x    = (const float*)d_in[0];
    const int*   gid  = (const int*)d_in[1];
    const float* ln1s = (const float*)d_in[2];
    const float* ln1b = (const float*)d_in[3];
    const float* ck   = (const float*)d_in[4];
    const float* cb   = (const float*)d_in[5];
    const float* ln2s = (const float*)d_in[6];
    const float* ln2b = (const float*)d_in[7];
    const float* wq   = (const float*)d_in[8];
    const float* bq   = (const float*)d_in[9];
    const float* wk   = (const float*)d_in[10];
    const float* bk   = (const float*)d_in[11];
    const float* wv   = (const float*)d_in[12];
    const float* bv   = (const float*)d_in[13];
    const float* wo   = (const float*)d_in[14];
    const float* bo   = (const float*)d_in[15];
    const float* w1   = (const float*)d_in[16];
    const float* b1   = (const float*)d_in[17];
    const float* w2   = (const float*)d_in[18];
    const float* b2   = (const float*)d_in[19];
    float* out = (float*)d_out;

    __half* d_hck; cudaGetSymbolAddress((void**)&d_hck, hck);
    __half* d_hwq; cudaGetSymbolAddress((void**)&d_hwq, hwq);
    __half* d_hwk; cudaGetSymbolAddress((void**)&d_hwk, hwk);
    __half* d_hwv; cudaGetSymbolAddress((void**)&d_hwv, hwv);
    __half* d_hwo; cudaGetSymbolAddress((void**)&d_hwo, hwo);
    __half* d_hw1; cudaGetSymbolAddress((void**)&d_hw1, hw1);
    __half* d_hw2; cudaGetSymbolAddress((void**)&d_hw2, hw2);

    cvt(ck, d_hck, (size_t)KC * Dc * Dc);
    cvt(wq, d_hwq, (size_t)Dc * Dc);
    cvt(wk, d_hwk, (size_t)Dc * Dc);
    cvt(wv, d_hwv, (size_t)Dc * Dc);
    cvt(wo, d_hwo, (size_t)Dc * Dc);
    cvt(w1, d_hw1, (size_t)Gc * Ec * Dc * FFc);
    cvt(w2, d_hw2, (size_t)Gc * Ec * FFc * Dc);

    ln_kernel<0><<<Nc, 256>>>(x, ln1s, ln1b);
    {
        ConvProb p{cb, x};
        launch_gemm(dim3(Dc / 128, Nc / 64, 1), p);
    }
    ln_kernel<1><<<Nc, 256>>>(x, ln2s, ln2b);
    {
        QKVProb p;
        p.b[0] = bq; p.b[1] = bk; p.b[2] = bv;
        launch_gemm(dim3(Dc / 128, Nc / 64, 3), p);
    }
    flash_kernel<<<dim3(Sc / 128, Bc * Hc), 256>>>();
    {
        OutProb p{bo};
        launch_gemm(dim3(Dc / 128, Nc / 64, 1), p);
    }
    zero_cnt_kernel<<<1, 32>>>();
    scatter_kernel<<<Nc / 256, 256>>>(gid);
    {
        Moe1Prob p{b1};
        launch_gemm(dim3(FFc / 128, Nc / 64, Gc * Ec), p);
    }
    {
        Moe2Prob p{b2, out};
        launch_gemm(dim3(Dc / 128, Nc / 64, Gc), p);
    }
}